// round 10
// baseline (speedup 1.0000x reference)
#include <cuda_runtime.h>
#include <cuda_bf16.h>
#include <cuda_fp16.h>
#include <cstdint>

#define NN     4096
#define DM     128
#define QK     32
#define HEADS  8

// ---------------- device scratch (no allocation allowed) ----------------
__device__ static __half         g_xh[NN * 128];                  // x, fp16
__device__ static __half         g_qh[NN * 256];                  // Q*qs, fp16 [node][h*32+d]
__device__ static __half         g_kh[NN * 256];                  // K, fp16
__device__ static __half         g_vt[(size_t)1024 * NN];         // [h*128+d][node], fp16
__device__ static __half         g_attnh[(size_t)NN * 1024];      // attention out, fp16
__device__ static __half         g_wqt[256 * 128];                // Wq^T [out][in] fp16
__device__ static __half         g_wkt[256 * 128];
__device__ static __half         g_wvt[1024 * 128];
__device__ static __half         g_wot[128 * 1024];               // Wo^T [128][1024]
__device__ static float          g_l[HEADS * NN];                 // row sums of scaled P
__device__ static __half         g_p[(size_t)HEADS * NN * NN];    // 256 MB, [h][row][key]
__device__ static unsigned       g_maskbits[(NN / 32) * NN];      // [wordIdx][row]
__device__ static int            g_mask_mode;

// ---------------- helpers ----------------
__device__ __forceinline__ void mma_f16(float* d, const uint32_t* a, uint32_t b0, uint32_t b1)
{
    asm volatile("mma.sync.aligned.m16n8k16.row.col.f32.f16.f16.f32 "
                 "{%0,%1,%2,%3}, {%4,%5,%6,%7}, {%8,%9}, {%0,%1,%2,%3};"
                 : "+f"(d[0]), "+f"(d[1]), "+f"(d[2]), "+f"(d[3])
                 : "r"(a[0]), "r"(a[1]), "r"(a[2]), "r"(a[3]), "r"(b0), "r"(b1));
}
__device__ __forceinline__ void ldmx4(uint32_t* r, uint32_t addr)
{
    asm volatile("ldmatrix.sync.aligned.m8n8.x4.shared.b16 {%0,%1,%2,%3}, [%4];"
                 : "=r"(r[0]), "=r"(r[1]), "=r"(r[2]), "=r"(r[3]) : "r"(addr));
}
__device__ __forceinline__ unsigned h2pack(float lo, float hi) {
    __half2 h = __floats2half2_rn(lo, hi);
    return *reinterpret_cast<unsigned*>(&h);
}
__device__ __forceinline__ void cp_async16(uint32_t smem_u32, const void* gptr) {
    asm volatile("cp.async.cg.shared.global [%0], [%1], 16;" :: "r"(smem_u32), "l"(gptr));
}

// ---------------- mask dtype detection ----------------
__global__ void detect_mask_kernel(const unsigned* __restrict__ m) {
    if (threadIdx.x == 0) {
        bool is_i32 = true, is_f32 = true;
        for (int i = 0; i < 256; i++) {
            unsigned w = m[i];
            if (w > 1u) is_i32 = false;
            if (w != 0u && w != 0x3F800000u) is_f32 = false;
        }
        g_mask_mode = is_i32 ? 1 : (is_f32 ? 2 : 0);
    }
}

// ---------------- mask bit packing (transposed output) ----------------
__global__ void pack_mask_kernel(const void* __restrict__ mraw) {
    int gid = blockIdx.x * blockDim.x + threadIdx.x;
    if (gid >= (NN / 32) * NN) return;
    int r  = gid & (NN - 1);
    int wi = gid >> 12;
    int mode = g_mask_mode;
    size_t base = (size_t)r * NN + (size_t)wi * 32;
    unsigned bits = 0;
    if (mode == 1) {
        const int* p = (const int*)mraw;
        #pragma unroll
        for (int b = 0; b < 32; b++) bits |= (unsigned)(p[base + b] != 0) << b;
    } else if (mode == 2) {
        const float* p = (const float*)mraw;
        #pragma unroll
        for (int b = 0; b < 32; b++) bits |= (unsigned)(p[base + b] != 0.0f) << b;
    } else {
        const unsigned char* p = (const unsigned char*)mraw;
        #pragma unroll
        for (int b = 0; b < 32; b++) bits |= (unsigned)(p[base + b] != 0) << b;
    }
    g_maskbits[(size_t)wi * NN + r] = bits;
}

// ---------------- prep: x -> fp16 ----------------
__global__ void convert_x_kernel(const float* __restrict__ x) {
    int gid = blockIdx.x * 256 + threadIdx.x;
    if (gid < NN * 128) g_xh[gid] = __float2half(x[gid]);
}
// W [K][N] fp32 -> Wt [N][K] fp16
__global__ void transposew_kernel(const float* __restrict__ W, __half* __restrict__ Wt,
                                  int K, int N) {
    int gid = blockIdx.x * 256 + threadIdx.x;
    if (gid >= K * N) return;
    int n = gid / K, k = gid - n * K;
    Wt[gid] = __float2half(W[(size_t)k * N + n]);
}

// ---------------- shared hgemm tile constants ----------------
#define HG_BUF   18432
#define HG_BOFF  36864
#define HG_SMEM  73728

// ---------------- fused Q/K/V projection (fp16 mma) ----------------
// grid.x: 0,1 -> Q cols 0..255 | 2,3 -> K | 4..11 -> V. grid.y: 32 row tiles.
// C[128m][128n] = xh[128][128] @ Wt[n][128]; epilogues: Q scaled fp16, K fp16,
// V fp16 transposed into g_vt[n][m].
__global__ __launch_bounds__(256, 2) void proj_kernel(
    const float* __restrict__ bq, const float* __restrict__ bk, const float* __restrict__ bv)
{
    extern __shared__ unsigned char sm2[];

    const int tid  = threadIdx.x;
    const int lane = tid & 31;
    const int warp = tid >> 5;
    const int g    = lane >> 2;
    const int tig  = lane & 3;
    const int cb   = blockIdx.x;
    const int row0 = blockIdx.y * 128;
    const int rg   = (warp & 3) * 32;
    const int dof  = (warp >> 2) * 64;

    int mode, colbase;
    const __half* wt;
    const float* bias;
    if (cb < 2)      { mode = 0; colbase = cb * 128;       wt = g_wqt; bias = bq; }
    else if (cb < 4) { mode = 1; colbase = (cb - 2) * 128; wt = g_wkt; bias = bk; }
    else             { mode = 2; colbase = (cb - 4) * 128; wt = g_wvt; bias = bv; }
    wt += (size_t)colbase * 128;

    const uint32_t smb = (uint32_t)__cvta_generic_to_shared(sm2);
    const char* ap = (const char*)g_xh + (size_t)row0 * 256;
    const char* bp = (const char*)wt;

    // both K-tiles (K=128 -> 2 x 64)
    #pragma unroll
    for (int t = 0; t < 2; t++) {
        #pragma unroll
        for (int it = 0; it < 4; it++) {
            int idx = it * 256 + tid, r = idx >> 3, ch = idx & 7;
            cp_async16(smb + t * HG_BUF + r * 144 + ch * 16,
                       ap + (size_t)r * 256 + t * 128 + ch * 16);
            cp_async16(smb + HG_BOFF + t * HG_BUF + r * 144 + ch * 16,
                       bp + (size_t)r * 256 + t * 128 + ch * 16);
        }
        asm volatile("cp.async.commit_group;");
    }
    asm volatile("cp.async.wait_group 0;");
    __syncthreads();

    const int aquad   = lane >> 4;
    const int arow_in = lane & 15;
    const int bquad   = lane >> 3;
    const int brow_in = (lane & 7) + ((bquad >> 1) << 3);
    const int bkcol   = (bquad & 1) << 3;

    float o[2][8][4] = {};
    #pragma unroll
    for (int t = 0; t < 2; t++) {
        const uint32_t psb = smb + t * HG_BUF;
        const uint32_t vtb = smb + HG_BOFF + t * HG_BUF;
        #pragma unroll
        for (int kf = 0; kf < 4; kf++) {
            uint32_t a0r[4], a1r[4];
            ldmx4(a0r, psb + ((rg + arow_in) * 72 + kf * 16 + aquad * 8) * 2);
            ldmx4(a1r, psb + ((rg + 16 + arow_in) * 72 + kf * 16 + aquad * 8) * 2);
            #pragma unroll
            for (int nbp = 0; nbp < 4; nbp++) {
                uint32_t br[4];
                const int nrow = dof + nbp * 16 + brow_in;
                ldmx4(br, vtb + (nrow * 72 + kf * 16 + bkcol) * 2);
                mma_f16(o[0][2 * nbp],     a0r, br[0], br[1]);
                mma_f16(o[0][2 * nbp + 1], a0r, br[2], br[3]);
                mma_f16(o[1][2 * nbp],     a1r, br[0], br[1]);
                mma_f16(o[1][2 * nbp + 1], a1r, br[2], br[3]);
            }
        }
    }

    if (mode < 2) {
        const float qs = (mode == 0) ? 0.17677669529663687f : 1.0f;
        __half* dst = (mode == 0) ? g_qh : g_kh;
        #pragma unroll
        for (int f = 0; f < 2; f++) {
            const int lr1 = rg + f * 16 + g, lr2 = lr1 + 8;
            #pragma unroll
            for (int nb = 0; nb < 8; nb++) {
                const int cg = colbase + dof + nb * 8 + 2 * tig;
                const float b0 = bias[cg], b1 = bias[cg + 1];
                *(unsigned*)(dst + (size_t)(row0 + lr1) * 256 + cg) =
                    h2pack((o[f][nb][0] + b0) * qs, (o[f][nb][1] + b1) * qs);
                *(unsigned*)(dst + (size_t)(row0 + lr2) * 256 + cg) =
                    h2pack((o[f][nb][2] + b0) * qs, (o[f][nb][3] + b1) * qs);
            }
        }
    } else {
        __syncthreads();
        __half* ct = (__half*)sm2;   // [128 cols][136] transpose staging
        #pragma unroll
        for (int f = 0; f < 2; f++) {
            const int lr1 = rg + f * 16 + g, lr2 = lr1 + 8;
            #pragma unroll
            for (int nb = 0; nb < 8; nb++) {
                const int cc = dof + nb * 8 + 2 * tig;
                const float b0 = bias[colbase + cc], b1 = bias[colbase + cc + 1];
                ct[cc * 136 + lr1]       = __float2half(o[f][nb][0] + b0);
                ct[(cc + 1) * 136 + lr1] = __float2half(o[f][nb][1] + b1);
                ct[cc * 136 + lr2]       = __float2half(o[f][nb][2] + b0);
                ct[(cc + 1) * 136 + lr2] = __float2half(o[f][nb][3] + b1);
            }
        }
        __syncthreads();
        const int c = tid >> 1, hh = tid & 1;
        const __half* src = ct + c * 136 + hh * 64;
        __half* dst = g_vt + (size_t)(colbase + c) * NN + row0 + hh * 64;
        #pragma unroll
        for (int i = 0; i < 8; i++)          // FIX: 8 x uint4 = 64 halves (was 4)
            *(uint4*)(dst + i * 8) = *(const uint4*)(src + i * 8);
    }
}

// ---------------- out projection: out = attnh @ Wo + bo (fp16 mma, K=1024) --------
__global__ __launch_bounds__(256, 2) void outproj_kernel(const float* __restrict__ bo,
                                                         float* __restrict__ out)
{
    extern __shared__ unsigned char sm2[];

    const int tid  = threadIdx.x;
    const int lane = tid & 31;
    const int warp = tid >> 5;
    const int g    = lane >> 2;
    const int tig  = lane & 3;
    const int row0 = blockIdx.x * 128;
    const int rg   = (warp & 3) * 32;
    const int dof  = (warp >> 2) * 64;

    const uint32_t smb = (uint32_t)__cvta_generic_to_shared(sm2);
    const char* ap = (const char*)g_attnh + (size_t)row0 * 2048;   // lda = 1024 halves
    const char* bp = (const char*)g_wot;                           // ldb = 1024 halves

    const int aquad   = lane >> 4;
    const int arow_in = lane & 15;
    const int bquad   = lane >> 3;
    const int brow_in = (lane & 7) + ((bquad >> 1) << 3);
    const int bkcol   = (bquad & 1) << 3;

    float o[2][8][4] = {};

    #define OISSUE(t, buf) do {                                                  \
        _Pragma("unroll")                                                        \
        for (int it = 0; it < 4; it++) {                                         \
            int idx = it * 256 + tid, r = idx >> 3, ch = idx & 7;                \
            cp_async16(smb + (buf) * HG_BUF + r * 144 + ch * 16,                 \
                       ap + (size_t)r * 2048 + (t) * 128 + ch * 16);             \
            cp_async16(smb + HG_BOFF + (buf) * HG_BUF + r * 144 + ch * 16,       \
                       bp + (size_t)r * 2048 + (t) * 128 + ch * 16);             \
        }                                                                        \
        asm volatile("cp.async.commit_group;");                                  \
    } while (0)

    OISSUE(0, 0);

    for (int t = 0; t < 16; ++t) {
        const int cur = t & 1;
        if (t + 1 < 16) {
            OISSUE(t + 1, cur ^ 1);
            asm volatile("cp.async.wait_group 1;");
        } else {
            asm volatile("cp.async.wait_group 0;");
        }
        __syncthreads();

        const uint32_t psb = smb + cur * HG_BUF;
        const uint32_t vtb = smb + HG_BOFF + cur * HG_BUF;
        #pragma unroll
        for (int kf = 0; kf < 4; kf++) {
            uint32_t a0r[4], a1r[4];
            ldmx4(a0r, psb + ((rg + arow_in) * 72 + kf * 16 + aquad * 8) * 2);
            ldmx4(a1r, psb + ((rg + 16 + arow_in) * 72 + kf * 16 + aquad * 8) * 2);
            #pragma unroll
            for (int nbp = 0; nbp < 4; nbp++) {
                uint32_t br[4];
                const int nrow = dof + nbp * 16 + brow_in;
                ldmx4(br, vtb + (nrow * 72 + kf * 16 + bkcol) * 2);
                mma_f16(o[0][2 * nbp],     a0r, br[0], br[1]);
                mma_f16(o[0][2 * nbp + 1], a0r, br[2], br[3]);
                mma_f16(o[1][2 * nbp],     a1r, br[0], br[1]);
                mma_f16(o[1][2 * nbp + 1], a1r, br[2], br[3]);
            }
        }
        __syncthreads();
    }

    #pragma unroll
    for (int f = 0; f < 2; f++) {
        const int lr1 = rg + f * 16 + g, lr2 = lr1 + 8;
        #pragma unroll
        for (int nb = 0; nb < 8; nb++) {
            const int c = dof + nb * 8 + 2 * tig;
            const float b0 = bo[c], b1 = bo[c + 1];
            float2 va; va.x = o[f][nb][0] + b0; va.y = o[f][nb][1] + b1;
            float2 vb; vb.x = o[f][nb][2] + b0; vb.y = o[f][nb][3] + b1;
            *(float2*)(out + (size_t)(row0 + lr1) * 128 + c) = va;
            *(float2*)(out + (size_t)(row0 + lr2) * 128 + c) = vb;
        }
    }
}

// ---------------- pass 1: P = exp(mask(QK^T+bias) - 6ln2), fp16 -> gmem ----------
// CTA = 128 rows x 1 head, 8 warps x 16 rows, 64-key tiles, fp16 m16n8k16 QK^T.
__global__ __launch_bounds__(256, 2) void attn_s_kernel(const float* __restrict__ ebias)
{
    __shared__ __half KT[2][64 * 40];

    const int tid  = threadIdx.x;
    const int lane = tid & 31;
    const int warp = tid >> 5;
    const int g    = lane >> 2;
    const int tig  = lane & 3;
    const int head = blockIdx.y;
    const int row0 = blockIdx.x * 128;
    const int r1   = row0 + warp * 16 + g;
    const int r2   = r1 + 8;
    const float ESH = 4.1588830833596715f;   // 6*ln2

    const int skey = tid >> 2;
    const int sseg = tid & 3;

    const uint32_t ktb = (uint32_t)__cvta_generic_to_shared(KT);
    const int bquad   = lane >> 3;
    const int brow_in = (lane & 7) + ((bquad >> 1) << 3);
    const int bkcol   = (bquad & 1) << 3;

    // Q fragments: direct fp16 loads (scale pre-folded in projection)
    uint32_t qa[2][4];
    {
        const __half* q1 = g_qh + (size_t)r1 * 256 + head * 32;
        const __half* q2 = g_qh + (size_t)r2 * 256 + head * 32;
        #pragma unroll
        for (int ks = 0; ks < 2; ks++) {
            const int k0 = ks * 16 + 2 * tig;
            qa[ks][0] = *(const uint32_t*)(q1 + k0);
            qa[ks][1] = *(const uint32_t*)(q2 + k0);
            qa[ks][2] = *(const uint32_t*)(q1 + k0 + 8);
            qa[ks][3] = *(const uint32_t*)(q2 + k0 + 8);
        }
    }

    float la1 = 0.f, la2 = 0.f;
    __half* pbase = g_p + ((size_t)head << 24);

    {
        const __half* kp = g_kh + (size_t)skey * 256 + head * 32 + sseg * 8;
        *(uint4*)&KT[0][skey * 40 + sseg * 8] = *(const uint4*)kp;
    }

    for (int t = 0; t < NN / 64; ++t) {
        __syncthreads();
        const int cur = t & 1;
        const int col0 = t * 64;

        uint4 pk;
        const bool pf = (t + 1 < NN / 64);
        if (pf)
            pk = *(const uint4*)(g_kh + (size_t)((t + 1) * 64 + skey) * 256
                                 + head * 32 + sseg * 8);

        float s[8][4];
        #pragma unroll
        for (int nb = 0; nb < 8; nb++) { s[nb][0] = s[nb][1] = s[nb][2] = s[nb][3] = 0.f; }
        #pragma unroll
        for (int ks = 0; ks < 2; ks++) {
            #pragma unroll
            for (int nbp = 0; nbp < 4; nbp++) {
                uint32_t br[4];
                const int krow = nbp * 16 + brow_in;
                ldmx4(br, ktb + cur * (64 * 40 * 2) + (krow * 40 + ks * 16 + bkcol) * 2);
                mma_f16(s[2 * nbp],     qa[ks], br[0], br[1]);
                mma_f16(s[2 * nbp + 1], qa[ks], br[2], br[3]);
            }
        }

        if (head == 0) {
            #pragma unroll
            for (int nb = 0; nb < 8; nb++) {
                float2 b01 = *(const float2*)(ebias + (size_t)r1 * NN + col0 + nb * 8 + 2 * tig);
                float2 b23 = *(const float2*)(ebias + (size_t)r2 * NN + col0 + nb * 8 + 2 * tig);
                s[nb][0] += b01.x; s[nb][1] += b01.y;
                s[nb][2] += b23.x; s[nb][3] += b23.y;
            }
        }
        {
            const unsigned w1a = g_maskbits[(size_t)(2 * t) * NN + r1];
            const unsigned w1b = g_maskbits[(size_t)(2 * t + 1) * NN + r1];
            const unsigned w2a = g_maskbits[(size_t)(2 * t) * NN + r2];
            const unsigned w2b = g_maskbits[(size_t)(2 * t + 1) * NN + r2];
            #pragma unroll
            for (int nb = 0; nb < 8; nb++) {
                const unsigned wr1 = (nb < 4) ? w1a : w1b;
                const unsigned wr2 = (nb < 4) ? w2a : w2b;
                const int c = (nb & 3) * 8 + 2 * tig;
                if ((wr1 >> c) & 1u)       s[nb][0] = -1e9f;
                if ((wr1 >> (c + 1)) & 1u) s[nb][1] = -1e9f;
                if ((wr2 >> c) & 1u)       s[nb][2] = -1e9f;
                if ((wr2 >> (c + 1)) & 1u) s[nb][3] = -1e9f;
            }
        }

        #pragma unroll
        for (int nb = 0; nb < 8; nb++) {
            float p0 = __expf(s[nb][0] - ESH);
            float p1 = __expf(s[nb][1] - ESH);
            float p2 = __expf(s[nb][2] - ESH);
            float p3 = __expf(s[nb][3] - ESH);
            unsigned u1 = h2pack(p0, p1);
            unsigned u2 = h2pack(p2, p3);
            __half2 h1 = *reinterpret_cast<__half2*>(&u1);
            __half2 h2v = *reinterpret_cast<__half2*>(&u2);
            float2 f1 = __half22float2(h1);
            float2 f2 = __half22float2(h2v);
            la1 += f1.x + f1.y;
            la2 += f2.x + f2.y;
            *(unsigned*)(pbase + (size_t)r1 * NN + col0 + nb * 8 + 2 * tig) = u1;
            *(unsigned*)(pbase + (size_t)r2 * NN + col0 + nb * 8 + 2 * tig) = u2;
        }

        if (pf)
            *(uint4*)&KT[cur ^ 1][skey * 40 + sseg * 8] = pk;
    }

    la1 += __shfl_xor_sync(0xffffffffu, la1, 1);
    la1 += __shfl_xor_sync(0xffffffffu, la1, 2);
    la2 += __shfl_xor_sync(0xffffffffu, la2, 1);
    la2 += __shfl_xor_sync(0xffffffffu, la2, 2);
    if (tig == 0) {
        g_l[head * NN + r1] = la1;
        g_l[head * NN + r2] = la2;
    }
}

// ---------------- pass 2: O = (P V) / l, fp16 GEMM, writes fp16 g_attnh ----------
#define P2_BUF   18432
#define P2_VTOFF 36864
#define P2_SMEM  73728

__global__ __launch_bounds__(256, 2) void attn_pv_kernel()
{
    extern __shared__ unsigned char sm2[];

    const int tid  = threadIdx.x;
    const int lane = tid & 31;
    const int warp = tid >> 5;
    const int g    = lane >> 2;
    const int tig  = lane & 3;
    const int head = blockIdx.y;
    const int row0 = blockIdx.x * 128;
    const int rg   = (warp & 3) * 32;
    const int dof  = (warp >> 2) * 64;

    const uint32_t smb = (uint32_t)__cvta_generic_to_shared(sm2);
    const char* pp0 = (const char*)(g_p + ((size_t)head << 24) + (size_t)row0 * NN);
    const char* vv0 = (const char*)(g_vt + (size_t)(head * 128) * NN);

    const int aquad   = lane >> 4;
    const int arow_in = lane & 15;
    const int bquad   = lane >> 3;
    const int brow_in = (lane & 7) + ((bquad >> 1) << 3);
    const int bkcol   = (bquad & 1) << 3;

    float o[2][8][4] = {};

    #define ISSUE(t, buf) do {                                                   \
        const char* pp = pp0 + (size_t)(t) * 128;                                \
        const char* vv = vv0 + (size_t)(t) * 128;                                \
        _Pragma("unroll")                                                        \
        for (int it = 0; it < 4; it++) {                                         \
            int idx = it * 256 + tid, row = idx >> 3, ch = idx & 7;              \
            cp_async16(smb + (buf) * P2_BUF + row * 144 + ch * 16,               \
                       pp + (size_t)row * (NN * 2) + ch * 16);                   \
            cp_async16(smb + P2_VTOFF + (buf) * P2_BUF + row * 144 + ch * 16,    \
                       vv + (size_t)row * (NN * 2) + ch * 16);                   \
        }                                                                        \
        asm volatile("cp.async.commit_group;");                                  \
    } while (0)

    ISSUE(0, 0);

    for (int t = 0; t < NN / 64; ++t) {
        const int cur = t & 1;
        if (t + 1 < NN / 64) {
            ISSUE(t + 1, cur ^ 1);
            asm volatile("cp.async.wait_group 1;");
        } else {
            asm volatile("cp.async.wait_group 0;");
        }
        __syncthreads();

        const uint32_t psb = smb + cur * P2_BUF;
        const uint32_t vtb = smb + P2_VTOFF + cur * P2_BUF;

        #pragma unroll
        for (int kf = 0; kf < 4; kf++) {
            uint32_t a0r[4], a1r[4];
            ldmx4(a0r, psb + ((rg + arow_in) * 72 + kf * 16 + aquad * 8) * 2);
            ldmx4(a1r, psb + ((rg + 16 + arow_in) * 72 + kf * 16 + aquad * 8) * 2);
            #pragma unroll
            for (int nbp = 0; nbp < 4; nbp++) {
                uint32_t br[4];
                const int nrow = dof + nbp * 16 + brow_in;
                ldmx4(br, vtb + (nrow * 72 + kf * 16 + bkcol) * 2);
                mma_f16(o[0][2 * nbp],     a0r, br[0], br[1]);
                mma_f16(o[0][2 * nbp + 1], a0r, br[2], br[3]);
                mma_f16(o[1][2 * nbp],     a1r, br[0], br[1]);
                mma_f16(o[1][2 * nbp + 1], a1r, br[2], br[3]);
            }
        }
        __syncthreads();
    }

    #pragma unroll
    for (int f = 0; f < 2; f++) {
        const int lr1 = rg + f * 16 + g;
        const int lr2 = lr1 + 8;
        const float i1 = 1.f / g_l[head * NN + row0 + lr1];
        const float i2 = 1.f / g_l[head * NN + row0 + lr2];
        __half* p1 = g_attnh + (size_t)(row0 + lr1) * 1024 + head * 128 + dof;
        __half* p2 = g_attnh + (size_t)(row0 + lr2) * 1024 + head * 128 + dof;
        #pragma unroll
        for (int nb = 0; nb < 8; nb++) {
            const int c = nb * 8 + 2 * tig;
            *(unsigned*)(p1 + c) = h2pack(o[f][nb][0] * i1, o[f][nb][1] * i1);
            *(unsigned*)(p2 + c) = h2pack(o[f][nb][2] * i2, o[f][nb][3] * i2);
        }
    }
}

// ---------------- launch ----------------
extern "C" void kernel_launch(void* const* d_in, const int* in_sizes, int n_in,
                              void* d_out, int out_size)
{
    const float* x     = (const float*)d_in[0];
    const void*  mask  = (const void*) d_in[1];
    const float* ebias = (const float*)d_in[2];
    const float* Wq    = (const float*)d_in[3];
    const float* bq    = (const float*)d_in[4];
    const float* Wk    = (const float*)d_in[5];
    const float* bk    = (const float*)d_in[6];
    const float* Wv    = (const float*)d_in[7];
    const float* bv    = (const float*)d_in[8];
    const float* Wo    = (const float*)d_in[9];
    const float* bo    = (const float*)d_in[10];
    float* out = (float*)d_out;

    __half *wqt, *wkt, *wvt, *wot;
    cudaGetSymbolAddress((void**)&wqt, g_wqt);
    cudaGetSymbolAddress((void**)&wkt, g_wkt);
    cudaGetSymbolAddress((void**)&wvt, g_wvt);
    cudaGetSymbolAddress((void**)&wot, g_wot);

    static bool attr_done = false;
    if (!attr_done) {
        cudaFuncSetAttribute(attn_pv_kernel, cudaFuncAttributeMaxDynamicSharedMemorySize,
                             P2_SMEM);
        cudaFuncSetAttribute(proj_kernel, cudaFuncAttributeMaxDynamicSharedMemorySize,
                             HG_SMEM);
        cudaFuncSetAttribute(outproj_kernel, cudaFuncAttributeMaxDynamicSharedMemorySize,
                             HG_SMEM);
        attr_done = true;
    }

    detect_mask_kernel<<<1, 32>>>((const unsigned*)mask);
    pack_mask_kernel<<<((NN / 32) * NN + 255) / 256, 256>>>(mask);

    convert_x_kernel<<<(NN * 128 + 255) / 256, 256>>>(x);
    transposew_kernel<<<(128 * 256 + 255) / 256, 256>>>(Wq, wqt, 128, 256);
    transposew_kernel<<<(128 * 256 + 255) / 256, 256>>>(Wk, wkt, 128, 256);
    transposew_kernel<<<(128 * 1024 + 255) / 256, 256>>>(Wv, wvt, 128, 1024);
    transposew_kernel<<<(1024 * 128 + 255) / 256, 256>>>(Wo, wot, 1024, 128);

    proj_kernel<<<dim3(12, NN / 128), 256, HG_SMEM>>>(bq, bk, bv);

    attn_s_kernel<<<dim3(NN / 128, HEADS), 256>>>(ebias);
    attn_pv_kernel<<<dim3(NN / 128, HEADS), 256, P2_SMEM>>>();

    outproj_kernel<<<NN / 128, 256, HG_SMEM>>>(bo, out);
}

// round 12
// speedup vs baseline: 1.3393x; 1.3393x over previous
#include <cuda_runtime.h>
#include <cuda_bf16.h>
#include <cuda_fp16.h>
#include <cstdint>

#define NN     4096
#define DM     128
#define QK     32
#define HEADS  8

// ---------------- device scratch (no allocation allowed) ----------------
__device__ static float          g_q[NN * 256];                   // [node][h*32+d]
__device__ static float          g_k[NN * 256];
__device__ static __half         g_vt[(size_t)1024 * NN];         // [h*128+d][node], fp16
__device__ static __half         g_attnh[(size_t)NN * 1024];      // attention out, fp16
__device__ static __half         g_wot[128 * 1024];               // Wo^T [128][1024] fp16
__device__ static float          g_l[HEADS * NN];                 // row sums of scaled P
__device__ static __half         g_p[(size_t)HEADS * NN * NN];    // 256 MB, [h][row][key]
__device__ static unsigned       g_maskbits[(NN / 32) * NN];      // [wordIdx][row]
__device__ static int            g_mask_mode;

// ---------------- helpers ----------------
__device__ __forceinline__ void mma_f16(float* d, const uint32_t* a, uint32_t b0, uint32_t b1)
{
    asm volatile("mma.sync.aligned.m16n8k16.row.col.f32.f16.f16.f32 "
                 "{%0,%1,%2,%3}, {%4,%5,%6,%7}, {%8,%9}, {%0,%1,%2,%3};"
                 : "+f"(d[0]), "+f"(d[1]), "+f"(d[2]), "+f"(d[3])
                 : "r"(a[0]), "r"(a[1]), "r"(a[2]), "r"(a[3]), "r"(b0), "r"(b1));
}
__device__ __forceinline__ void ldmx4(uint32_t* r, uint32_t addr)
{
    asm volatile("ldmatrix.sync.aligned.m8n8.x4.shared.b16 {%0,%1,%2,%3}, [%4];"
                 : "=r"(r[0]), "=r"(r[1]), "=r"(r[2]), "=r"(r[3]) : "r"(addr));
}
__device__ __forceinline__ unsigned h2pack(float lo, float hi) {
    __half2 h = __floats2half2_rn(lo, hi);
    return *reinterpret_cast<unsigned*>(&h);
}
__device__ __forceinline__ void cp_async16(uint32_t smem_u32, const void* gptr) {
    asm volatile("cp.async.cg.shared.global [%0], [%1], 16;" :: "r"(smem_u32), "l"(gptr));
}

// ---------------- mask dtype detection ----------------
__global__ void detect_mask_kernel(const unsigned* __restrict__ m) {
    if (threadIdx.x == 0) {
        bool is_i32 = true, is_f32 = true;
        for (int i = 0; i < 256; i++) {
            unsigned w = m[i];
            if (w > 1u) is_i32 = false;
            if (w != 0u && w != 0x3F800000u) is_f32 = false;
        }
        g_mask_mode = is_i32 ? 1 : (is_f32 ? 2 : 0);
    }
}

// ---------------- mask bit packing (transposed output) ----------------
__global__ void pack_mask_kernel(const void* __restrict__ mraw) {
    int gid = blockIdx.x * blockDim.x + threadIdx.x;
    if (gid >= (NN / 32) * NN) return;
    int r  = gid & (NN - 1);
    int wi = gid >> 12;
    int mode = g_mask_mode;
    size_t base = (size_t)r * NN + (size_t)wi * 32;
    unsigned bits = 0;
    if (mode == 1) {
        const int* p = (const int*)mraw;
        #pragma unroll
        for (int b = 0; b < 32; b++) bits |= (unsigned)(p[base + b] != 0) << b;
    } else if (mode == 2) {
        const float* p = (const float*)mraw;
        #pragma unroll
        for (int b = 0; b < 32; b++) bits |= (unsigned)(p[base + b] != 0.0f) << b;
    } else {
        const unsigned char* p = (const unsigned char*)mraw;
        #pragma unroll
        for (int b = 0; b < 32; b++) bits |= (unsigned)(p[base + b] != 0) << b;
    }
    g_maskbits[(size_t)wi * NN + r] = bits;
}

// ---------------- W [K][N] fp32 -> Wt [N][K] fp16 (Wo only) ----------------
__global__ void transposew_kernel(const float* __restrict__ W, __half* __restrict__ Wt,
                                  int K, int N) {
    int gid = blockIdx.x * 256 + threadIdx.x;
    if (gid >= K * N) return;
    int n = gid / K, k = gid - n * K;
    Wt[gid] = __float2half(W[(size_t)k * N + n]);
}

// ---------------- generic tiled GEMM: C[M,N] = A[M,K] @ B[K,N] + bias ----------------
__global__ __launch_bounds__(256) void gemm_bias_kernel(
    const float* __restrict__ A, const float* __restrict__ B,
    const float* __restrict__ bias, float* __restrict__ C,
    int M, int K, int N)
{
    __shared__ float Ast[16][68];
    __shared__ float Bs[16][64];

    const int tid = threadIdx.x;
    const int tx = tid & 15, ty = tid >> 4;
    const int n0 = blockIdx.x * 64, m0 = blockIdx.y * 64;

    const int am = tid >> 2;
    const int ak = (tid & 3) * 4;
    const int bk = tid >> 4;
    const int bn = (tid & 15) * 4;

    float acc[4][4] = {};

    for (int k0 = 0; k0 < K; k0 += 16) {
        float4 a4 = *(const float4*)(A + (size_t)(m0 + am) * K + k0 + ak);
        Ast[ak + 0][am] = a4.x; Ast[ak + 1][am] = a4.y;
        Ast[ak + 2][am] = a4.z; Ast[ak + 3][am] = a4.w;
        float4 b4 = *(const float4*)(B + (size_t)(k0 + bk) * N + n0 + bn);
        *(float4*)&Bs[bk][bn] = b4;
        __syncthreads();
        #pragma unroll
        for (int kk = 0; kk < 16; kk++) {
            float4 av = *(const float4*)&Ast[kk][ty * 4];
            float4 bv = *(const float4*)&Bs[kk][tx * 4];
            float aa[4] = {av.x, av.y, av.z, av.w};
            float bb[4] = {bv.x, bv.y, bv.z, bv.w};
            #pragma unroll
            for (int i = 0; i < 4; i++)
                #pragma unroll
                for (int j = 0; j < 4; j++)
                    acc[i][j] += aa[i] * bb[j];
        }
        __syncthreads();
    }
    #pragma unroll
    for (int i = 0; i < 4; i++) {
        const int m = m0 + ty * 4 + i;
        #pragma unroll
        for (int j = 0; j < 4; j++) {
            const int n = n0 + tx * 4 + j;
            C[(size_t)m * N + n] = acc[i][j] + bias[n];
        }
    }
}

// ---------------- V projection GEMM: writes transposed fp16 g_vt[n][m] ----------------
__global__ __launch_bounds__(256) void gemm_bias_vt_kernel(
    const float* __restrict__ A, const float* __restrict__ B,
    const float* __restrict__ bias, int M, int K, int N)
{
    __shared__ float Ast[16][68];
    __shared__ float Bs[16][64];

    const int tid = threadIdx.x;
    const int tx = tid & 15, ty = tid >> 4;
    const int n0 = blockIdx.x * 64, m0 = blockIdx.y * 64;

    const int am = tid >> 2;
    const int ak = (tid & 3) * 4;
    const int bk = tid >> 4;
    const int bn = (tid & 15) * 4;

    float acc[4][4] = {};

    for (int k0 = 0; k0 < K; k0 += 16) {
        float4 a4 = *(const float4*)(A + (size_t)(m0 + am) * K + k0 + ak);
        Ast[ak + 0][am] = a4.x; Ast[ak + 1][am] = a4.y;
        Ast[ak + 2][am] = a4.z; Ast[ak + 3][am] = a4.w;
        float4 b4 = *(const float4*)(B + (size_t)(k0 + bk) * N + n0 + bn);
        *(float4*)&Bs[bk][bn] = b4;
        __syncthreads();
        #pragma unroll
        for (int kk = 0; kk < 16; kk++) {
            float4 av = *(const float4*)&Ast[kk][ty * 4];
            float4 bv = *(const float4*)&Bs[kk][tx * 4];
            float aa[4] = {av.x, av.y, av.z, av.w};
            float bb[4] = {bv.x, bv.y, bv.z, bv.w};
            #pragma unroll
            for (int i = 0; i < 4; i++)
                #pragma unroll
                for (int j = 0; j < 4; j++)
                    acc[i][j] += aa[i] * bb[j];
        }
        __syncthreads();
    }
    const int m = m0 + ty * 4;
    #pragma unroll
    for (int j = 0; j < 4; j++) {
        const int n = n0 + tx * 4 + j;
        const float bj = bias[n];
        uint2 w;
        w.x = h2pack(acc[0][j] + bj, acc[1][j] + bj);
        w.y = h2pack(acc[2][j] + bj, acc[3][j] + bj);
        *(uint2*)((char*)g_vt + ((size_t)n * NN + m) * 2) = w;
    }
}

// ---------------- pass 1: P = exp(mask(QK^T/sqrt(d)+bias) - 6ln2), fp16 -> gmem --------
// CTA = 128 rows x 1 head, 8 warps x 16 rows, 64-key tiles. fp16 m16n8k16 QK^T,
// K fragments via ldmatrix from KT[key][qk] (stride 40 halves, conflict-free).
__global__ __launch_bounds__(256, 2) void attn_s_kernel(const float* __restrict__ ebias)
{
    __shared__ __half KT[2][64 * 40];

    const int tid  = threadIdx.x;
    const int lane = tid & 31;
    const int warp = tid >> 5;
    const int g    = lane >> 2;
    const int tig  = lane & 3;
    const int head = blockIdx.y;
    const int row0 = blockIdx.x * 128;
    const int r1   = row0 + warp * 16 + g;
    const int r2   = r1 + 8;
    const float ESH = 4.1588830833596715f;   // 6*ln2

    const int skey = tid >> 2;               // staging: key row 0..63
    const int sseg = tid & 3;                // staging: 8-dim segment

    const uint32_t ktb = (uint32_t)__cvta_generic_to_shared(KT);
    const int bquad   = lane >> 3;
    const int brow_in = (lane & 7) + ((bquad >> 1) << 3);
    const int bkcol   = (bquad & 1) << 3;

    // Q fragments (scaled, fp16): 2 ksteps x 4 regs
    uint32_t qa[2][4];
    {
        const float qs = 0.17677669529663687f;
        const float* q1 = g_q + (size_t)r1 * 256 + head * 32;
        const float* q2 = g_q + (size_t)r2 * 256 + head * 32;
        #pragma unroll
        for (int ks = 0; ks < 2; ks++) {
            const int k0 = ks * 16 + 2 * tig;
            qa[ks][0] = h2pack(q1[k0] * qs,     q1[k0 + 1] * qs);
            qa[ks][1] = h2pack(q2[k0] * qs,     q2[k0 + 1] * qs);
            qa[ks][2] = h2pack(q1[k0 + 8] * qs, q1[k0 + 9] * qs);
            qa[ks][3] = h2pack(q2[k0 + 8] * qs, q2[k0 + 9] * qs);
        }
    }

    float la1 = 0.f, la2 = 0.f;
    __half* pbase = g_p + ((size_t)head << 24);

    // prologue: stage tile 0
    {
        const float* kp = g_k + (size_t)skey * 256 + head * 32 + sseg * 8;
        float4 k0 = *(const float4*)kp;
        float4 k1 = *(const float4*)(kp + 4);
        uint4 w;
        w.x = h2pack(k0.x, k0.y); w.y = h2pack(k0.z, k0.w);
        w.z = h2pack(k1.x, k1.y); w.w = h2pack(k1.z, k1.w);
        *(uint4*)&KT[0][skey * 40 + sseg * 8] = w;
    }

    for (int t = 0; t < NN / 64; ++t) {
        __syncthreads();
        const int cur = t & 1;
        const int col0 = t * 64;

        float4 pk0, pk1;
        const bool pf = (t + 1 < NN / 64);
        if (pf) {
            const float* kp = g_k + (size_t)((t + 1) * 64 + skey) * 256 + head * 32 + sseg * 8;
            pk0 = *(const float4*)kp;
            pk1 = *(const float4*)(kp + 4);
        }

        // S = Q K^T (fp16 m16n8k16): 8 ldmatrix.x4 + 16 mma per warp
        float s[8][4];
        #pragma unroll
        for (int nb = 0; nb < 8; nb++) { s[nb][0] = s[nb][1] = s[nb][2] = s[nb][3] = 0.f; }
        #pragma unroll
        for (int ks = 0; ks < 2; ks++) {
            #pragma unroll
            for (int nbp = 0; nbp < 4; nbp++) {
                uint32_t br[4];
                const int krow = nbp * 16 + brow_in;
                ldmx4(br, ktb + cur * (64 * 40 * 2) + (krow * 40 + ks * 16 + bkcol) * 2);
                mma_f16(s[2 * nbp],     qa[ks], br[0], br[1]);
                mma_f16(s[2 * nbp + 1], qa[ks], br[2], br[3]);
            }
        }

        // edge bias (head 0 only)
        if (head == 0) {
            #pragma unroll
            for (int nb = 0; nb < 8; nb++) {
                float2 b01 = *(const float2*)(ebias + (size_t)r1 * NN + col0 + nb * 8 + 2 * tig);
                float2 b23 = *(const float2*)(ebias + (size_t)r2 * NN + col0 + nb * 8 + 2 * tig);
                s[nb][0] += b01.x; s[nb][1] += b01.y;
                s[nb][2] += b23.x; s[nb][3] += b23.y;
            }
        }
        // mask
        {
            const unsigned w1a = g_maskbits[(size_t)(2 * t) * NN + r1];
            const unsigned w1b = g_maskbits[(size_t)(2 * t + 1) * NN + r1];
            const unsigned w2a = g_maskbits[(size_t)(2 * t) * NN + r2];
            const unsigned w2b = g_maskbits[(size_t)(2 * t + 1) * NN + r2];
            #pragma unroll
            for (int nb = 0; nb < 8; nb++) {
                const unsigned wr1 = (nb < 4) ? w1a : w1b;
                const unsigned wr2 = (nb < 4) ? w2a : w2b;
                const int c = (nb & 3) * 8 + 2 * tig;
                if ((wr1 >> c) & 1u)       s[nb][0] = -1e9f;
                if ((wr1 >> (c + 1)) & 1u) s[nb][1] = -1e9f;
                if ((wr2 >> c) & 1u)       s[nb][2] = -1e9f;
                if ((wr2 >> (c + 1)) & 1u) s[nb][3] = -1e9f;
            }
        }

        // p = exp(s - 6ln2); accumulate l from ROUNDED fp16 values; store
        #pragma unroll
        for (int nb = 0; nb < 8; nb++) {
            float p0 = __expf(s[nb][0] - ESH);
            float p1 = __expf(s[nb][1] - ESH);
            float p2 = __expf(s[nb][2] - ESH);
            float p3 = __expf(s[nb][3] - ESH);
            unsigned u1 = h2pack(p0, p1);
            unsigned u2 = h2pack(p2, p3);
            __half2 h1 = *reinterpret_cast<__half2*>(&u1);
            __half2 h2v = *reinterpret_cast<__half2*>(&u2);
            float2 f1 = __half22float2(h1);
            float2 f2 = __half22float2(h2v);
            la1 += f1.x + f1.y;
            la2 += f2.x + f2.y;
            *(unsigned*)(pbase + (size_t)r1 * NN + col0 + nb * 8 + 2 * tig) = u1;
            *(unsigned*)(pbase + (size_t)r2 * NN + col0 + nb * 8 + 2 * tig) = u2;
        }

        // store prefetched K (fp16) into other buffer
        if (pf) {
            uint4 w;
            w.x = h2pack(pk0.x, pk0.y); w.y = h2pack(pk0.z, pk0.w);
            w.z = h2pack(pk1.x, pk1.y); w.w = h2pack(pk1.z, pk1.w);
            *(uint4*)&KT[cur ^ 1][skey * 40 + sseg * 8] = w;
        }
    }

    la1 += __shfl_xor_sync(0xffffffffu, la1, 1);
    la1 += __shfl_xor_sync(0xffffffffu, la1, 2);
    la2 += __shfl_xor_sync(0xffffffffu, la2, 1);
    la2 += __shfl_xor_sync(0xffffffffu, la2, 2);
    if (tig == 0) {
        g_l[head * NN + r1] = la1;
        g_l[head * NN + r2] = la2;
    }
}

// ---------------- pass 2: O = (P V) / l, fp16 GEMM, cp.async + ldmatrix ----------------
// CTA = 128 rows x 1 head. 8 warps = 4 rowgroups(32) x 2 dm-halves(64). 64-key tiles.
#define P2_BUF   18432
#define P2_VTOFF 36864
#define P2_SMEM  73728

__global__ __launch_bounds__(256, 2) void attn_pv_kernel()
{
    extern __shared__ unsigned char sm2[];

    const int tid  = threadIdx.x;
    const int lane = tid & 31;
    const int warp = tid >> 5;
    const int g    = lane >> 2;
    const int tig  = lane & 3;
    const int head = blockIdx.y;
    const int row0 = blockIdx.x * 128;
    const int rg   = (warp & 3) * 32;
    const int dof  = (warp >> 2) * 64;

    const uint32_t smb = (uint32_t)__cvta_generic_to_shared(sm2);
    const char* pp0 = (const char*)(g_p + ((size_t)head << 24) + (size_t)row0 * NN);
    const char* vv0 = (const char*)(g_vt + (size_t)(head * 128) * NN);

    const int aquad   = lane >> 4;
    const int arow_in = lane & 15;
    const int bquad   = lane >> 3;
    const int brow_in = (lane & 7) + ((bquad >> 1) << 3);
    const int bkcol   = (bquad & 1) << 3;

    float o[2][8][4] = {};

    #define ISSUE(t, buf) do {                                                   \
        const char* pp = pp0 + (size_t)(t) * 128;                                \
        const char* vv = vv0 + (size_t)(t) * 128;                                \
        _Pragma("unroll")                                                        \
        for (int it = 0; it < 4; it++) {                                         \
            int idx = it * 256 + tid, row = idx >> 3, ch = idx & 7;              \
            cp_async16(smb + (buf) * P2_BUF + row * 144 + ch * 16,               \
                       pp + (size_t)row * (NN * 2) + ch * 16);                   \
            cp_async16(smb + P2_VTOFF + (buf) * P2_BUF + row * 144 + ch * 16,    \
                       vv + (size_t)row * (NN * 2) + ch * 16);                   \
        }                                                                        \
        asm volatile("cp.async.commit_group;");                                  \
    } while (0)

    ISSUE(0, 0);

    for (int t = 0; t < NN / 64; ++t) {
        const int cur = t & 1;
        if (t + 1 < NN / 64) {
            ISSUE(t + 1, cur ^ 1);
            asm volatile("cp.async.wait_group 1;");
        } else {
            asm volatile("cp.async.wait_group 0;");
        }
        __syncthreads();

        const uint32_t psb = smb + cur * P2_BUF;
        const uint32_t vtb = smb + P2_VTOFF + cur * P2_BUF;

        #pragma unroll
        for (int kf = 0; kf < 4; kf++) {
            uint32_t a0r[4], a1r[4];
            ldmx4(a0r, psb + ((rg + arow_in) * 72 + kf * 16 + aquad * 8) * 2);
            ldmx4(a1r, psb + ((rg + 16 + arow_in) * 72 + kf * 16 + aquad * 8) * 2);
            #pragma unroll
            for (int nbp = 0; nbp < 4; nbp++) {
                uint32_t br[4];
                const int nrow = dof + nbp * 16 + brow_in;
                ldmx4(br, vtb + (nrow * 72 + kf * 16 + bkcol) * 2);
                mma_f16(o[0][2 * nbp],     a0r, br[0], br[1]);
                mma_f16(o[0][2 * nbp + 1], a0r, br[2], br[3]);
                mma_f16(o[1][2 * nbp],     a1r, br[0], br[1]);
                mma_f16(o[1][2 * nbp + 1], a1r, br[2], br[3]);
            }
        }
        __syncthreads();
    }

    // epilogue: scale by 1/l, write fp16 g_attnh
    #pragma unroll
    for (int f = 0; f < 2; f++) {
        const int lr1 = rg + f * 16 + g;
        const int lr2 = lr1 + 8;
        const float i1 = 1.f / g_l[head * NN + row0 + lr1];
        const float i2 = 1.f / g_l[head * NN + row0 + lr2];
        __half* p1 = g_attnh + (size_t)(row0 + lr1) * 1024 + head * 128 + dof;
        __half* p2 = g_attnh + (size_t)(row0 + lr2) * 1024 + head * 128 + dof;
        #pragma unroll
        for (int nb = 0; nb < 8; nb++) {
            const int c = nb * 8 + 2 * tig;
            *(unsigned*)(p1 + c) = h2pack(o[f][nb][0] * i1, o[f][nb][1] * i1);
            *(unsigned*)(p2 + c) = h2pack(o[f][nb][2] * i2, o[f][nb][3] * i2);
        }
    }
}

// ---------------- out projection: out = attnh @ Wo + bo (fp16 mma, K=1024) --------
__global__ __launch_bounds__(256, 2) void outproj_kernel(const float* __restrict__ bo,
                                                         float* __restrict__ out)
{
    extern __shared__ unsigned char sm2[];

    const int tid  = threadIdx.x;
    const int lane = tid & 31;
    const int warp = tid >> 5;
    const int g    = lane >> 2;
    const int tig  = lane & 3;
    const int row0 = blockIdx.x * 128;
    const int rg   = (warp & 3) * 32;
    const int dof  = (warp >> 2) * 64;

    const uint32_t smb = (uint32_t)__cvta_generic_to_shared(sm2);
    const char* ap = (const char*)g_attnh + (size_t)row0 * 2048;   // lda = 1024 halves
    const char* bp = (const char*)g_wot;                           // ldb = 1024 halves

    const int aquad   = lane >> 4;
    const int arow_in = lane & 15;
    const int bquad   = lane >> 3;
    const int brow_in = (lane & 7) + ((bquad >> 1) << 3);
    const int bkcol   = (bquad & 1) << 3;

    float o[2][8][4] = {};

    #define OISSUE(t, buf) do {                                                  \
        _Pragma("unroll")                                                        \
        for (int it = 0; it < 4; it++) {                                         \
            int idx = it * 256 + tid, r = idx >> 3, ch = idx & 7;                \
            cp_async16(smb + (buf) * P2_BUF + r * 144 + ch * 16,                 \
                       ap + (size_t)r * 2048 + (t) * 128 + ch * 16);             \
            cp_async16(smb + P2_VTOFF + (buf) * P2_BUF + r * 144 + ch * 16,      \
                       bp + (size_t)r * 2048 + (t) * 128 + ch * 16);             \
        }                                                                        \
        asm volatile("cp.async.commit_group;");                                  \
    } while (0)

    OISSUE(0, 0);

    for (int t = 0; t < 16; ++t) {
        const int cur = t & 1;
        if (t + 1 < 16) {
            OISSUE(t + 1, cur ^ 1);
            asm volatile("cp.async.wait_group 1;");
        } else {
            asm volatile("cp.async.wait_group 0;");
        }
        __syncthreads();

        const uint32_t psb = smb + cur * P2_BUF;
        const uint32_t vtb = smb + P2_VTOFF + cur * P2_BUF;
        #pragma unroll
        for (int kf = 0; kf < 4; kf++) {
            uint32_t a0r[4], a1r[4];
            ldmx4(a0r, psb + ((rg + arow_in) * 72 + kf * 16 + aquad * 8) * 2);
            ldmx4(a1r, psb + ((rg + 16 + arow_in) * 72 + kf * 16 + aquad * 8) * 2);
            #pragma unroll
            for (int nbp = 0; nbp < 4; nbp++) {
                uint32_t br[4];
                const int nrow = dof + nbp * 16 + brow_in;
                ldmx4(br, vtb + (nrow * 72 + kf * 16 + bkcol) * 2);
                mma_f16(o[0][2 * nbp],     a0r, br[0], br[1]);
                mma_f16(o[0][2 * nbp + 1], a0r, br[2], br[3]);
                mma_f16(o[1][2 * nbp],     a1r, br[0], br[1]);
                mma_f16(o[1][2 * nbp + 1], a1r, br[2], br[3]);
            }
        }
        __syncthreads();
    }

    #pragma unroll
    for (int f = 0; f < 2; f++) {
        const int lr1 = rg + f * 16 + g, lr2 = lr1 + 8;
        #pragma unroll
        for (int nb = 0; nb < 8; nb++) {
            const int c = dof + nb * 8 + 2 * tig;
            const float b0 = bo[c], b1 = bo[c + 1];
            float2 va; va.x = o[f][nb][0] + b0; va.y = o[f][nb][1] + b1;
            float2 vb; vb.x = o[f][nb][2] + b0; vb.y = o[f][nb][3] + b1;
            *(float2*)(out + (size_t)(row0 + lr1) * 128 + c) = va;
            *(float2*)(out + (size_t)(row0 + lr2) * 128 + c) = vb;
        }
    }
}

// ---------------- launch ----------------
extern "C" void kernel_launch(void* const* d_in, const int* in_sizes, int n_in,
                              void* d_out, int out_size)
{
    const float* x     = (const float*)d_in[0];
    const void*  mask  = (const void*) d_in[1];
    const float* ebias = (const float*)d_in[2];
    const float* Wq    = (const float*)d_in[3];
    const float* bq    = (const float*)d_in[4];
    const float* Wk    = (const float*)d_in[5];
    const float* bk    = (const float*)d_in[6];
    const float* Wv    = (const float*)d_in[7];
    const float* bv    = (const float*)d_in[8];
    const float* Wo    = (const float*)d_in[9];
    const float* bo    = (const float*)d_in[10];
    float* out = (float*)d_out;

    float *gq, *gk;
    __half *wot;
    cudaGetSymbolAddress((void**)&gq, g_q);
    cudaGetSymbolAddress((void**)&gk, g_k);
    cudaGetSymbolAddress((void**)&wot, g_wot);

    static bool attr_done = false;
    if (!attr_done) {
        cudaFuncSetAttribute(attn_pv_kernel, cudaFuncAttributeMaxDynamicSharedMemorySize,
                             P2_SMEM);
        cudaFuncSetAttribute(outproj_kernel, cudaFuncAttributeMaxDynamicSharedMemorySize,
                             P2_SMEM);
        attr_done = true;
    }

    detect_mask_kernel<<<1, 32>>>((const unsigned*)mask);
    pack_mask_kernel<<<((NN / 32) * NN + 255) / 256, 256>>>(mask);

    gemm_bias_kernel<<<dim3(256 / 64, NN / 64), 256>>>(x, Wq, bq, gq, NN, DM, QK * HEADS);
    gemm_bias_kernel<<<dim3(256 / 64, NN / 64), 256>>>(x, Wk, bk, gk, NN, DM, QK * HEADS);
    gemm_bias_vt_kernel<<<dim3(1024 / 64, NN / 64), 256>>>(x, Wv, bv, NN, DM, DM * HEADS);
    transposew_kernel<<<(1024 * 128 + 255) / 256, 256>>>(Wo, wot, 1024, 128);

    attn_s_kernel<<<dim3(NN / 128, HEADS), 256>>>(ebias);
    attn_pv_kernel<<<dim3(NN / 128, HEADS), 256, P2_SMEM>>>();

    outproj_kernel<<<NN / 128, 256, P2_SMEM>>>(bo, out);
}

// round 13
// speedup vs baseline: 1.4034x; 1.0478x over previous
#include <cuda_runtime.h>
#include <cuda_bf16.h>
#include <cuda_fp16.h>
#include <cstdint>

#define NN     4096
#define DM     128
#define QK     32
#define HEADS  8

// ---------------- device scratch (no allocation allowed) ----------------
__device__ static float          g_q[NN * 256];                   // [node][h*32+d]
__device__ static float          g_k[NN * 256];
__device__ static __half         g_vt[(size_t)1024 * NN];         // [h*128+d][node], fp16
__device__ static __half         g_attnh[(size_t)NN * 1024];      // attention out, fp16
__device__ static __half         g_wot[128 * 1024];               // Wo^T [128][1024] fp16
__device__ static unsigned       g_maskbits[(NN / 32) * NN];      // [wordIdx][row]
__device__ static int            g_mask_mode;

// ---------------- helpers ----------------
__device__ __forceinline__ void mma_f16(float* d, const uint32_t* a, uint32_t b0, uint32_t b1)
{
    asm volatile("mma.sync.aligned.m16n8k16.row.col.f32.f16.f16.f32 "
                 "{%0,%1,%2,%3}, {%4,%5,%6,%7}, {%8,%9}, {%0,%1,%2,%3};"
                 : "+f"(d[0]), "+f"(d[1]), "+f"(d[2]), "+f"(d[3])
                 : "r"(a[0]), "r"(a[1]), "r"(a[2]), "r"(a[3]), "r"(b0), "r"(b1));
}
__device__ __forceinline__ void ldmx4(uint32_t* r, uint32_t addr)
{
    asm volatile("ldmatrix.sync.aligned.m8n8.x4.shared.b16 {%0,%1,%2,%3}, [%4];"
                 : "=r"(r[0]), "=r"(r[1]), "=r"(r[2]), "=r"(r[3]) : "r"(addr));
}
__device__ __forceinline__ unsigned h2pack(float lo, float hi) {
    __half2 h = __floats2half2_rn(lo, hi);
    return *reinterpret_cast<unsigned*>(&h);
}
__device__ __forceinline__ void cp_async16(uint32_t smem_u32, const void* gptr) {
    asm volatile("cp.async.cg.shared.global [%0], [%1], 16;" :: "r"(smem_u32), "l"(gptr));
}

// ---------------- mask dtype detection ----------------
__global__ void detect_mask_kernel(const unsigned* __restrict__ m) {
    if (threadIdx.x == 0) {
        bool is_i32 = true, is_f32 = true;
        for (int i = 0; i < 256; i++) {
            unsigned w = m[i];
            if (w > 1u) is_i32 = false;
            if (w != 0u && w != 0x3F800000u) is_f32 = false;
        }
        g_mask_mode = is_i32 ? 1 : (is_f32 ? 2 : 0);
    }
}

// ---------------- mask bit packing (transposed output) ----------------
__global__ void pack_mask_kernel(const void* __restrict__ mraw) {
    int gid = blockIdx.x * blockDim.x + threadIdx.x;
    if (gid >= (NN / 32) * NN) return;
    int r  = gid & (NN - 1);
    int wi = gid >> 12;
    int mode = g_mask_mode;
    size_t base = (size_t)r * NN + (size_t)wi * 32;
    unsigned bits = 0;
    if (mode == 1) {
        const int* p = (const int*)mraw;
        #pragma unroll
        for (int b = 0; b < 32; b++) bits |= (unsigned)(p[base + b] != 0) << b;
    } else if (mode == 2) {
        const float* p = (const float*)mraw;
        #pragma unroll
        for (int b = 0; b < 32; b++) bits |= (unsigned)(p[base + b] != 0.0f) << b;
    } else {
        const unsigned char* p = (const unsigned char*)mraw;
        #pragma unroll
        for (int b = 0; b < 32; b++) bits |= (unsigned)(p[base + b] != 0) << b;
    }
    g_maskbits[(size_t)wi * NN + r] = bits;
}

// ---------------- W [K][N] fp32 -> Wt [N][K] fp16 (Wo only) ----------------
__global__ void transposew_kernel(const float* __restrict__ W, __half* __restrict__ Wt,
                                  int K, int N) {
    int gid = blockIdx.x * 256 + threadIdx.x;
    if (gid >= K * N) return;
    int n = gid / K, k = gid - n * K;
    Wt[gid] = __float2half(W[(size_t)k * N + n]);
}

// ---------------- generic tiled GEMM: C[M,N] = A[M,K] @ B[K,N] + bias ----------------
__global__ __launch_bounds__(256) void gemm_bias_kernel(
    const float* __restrict__ A, const float* __restrict__ B,
    const float* __restrict__ bias, float* __restrict__ C,
    int M, int K, int N)
{
    __shared__ float Ast[16][68];
    __shared__ float Bs[16][64];

    const int tid = threadIdx.x;
    const int tx = tid & 15, ty = tid >> 4;
    const int n0 = blockIdx.x * 64, m0 = blockIdx.y * 64;

    const int am = tid >> 2;
    const int ak = (tid & 3) * 4;
    const int bk = tid >> 4;
    const int bn = (tid & 15) * 4;

    float acc[4][4] = {};

    for (int k0 = 0; k0 < K; k0 += 16) {
        float4 a4 = *(const float4*)(A + (size_t)(m0 + am) * K + k0 + ak);
        Ast[ak + 0][am] = a4.x; Ast[ak + 1][am] = a4.y;
        Ast[ak + 2][am] = a4.z; Ast[ak + 3][am] = a4.w;
        float4 b4 = *(const float4*)(B + (size_t)(k0 + bk) * N + n0 + bn);
        *(float4*)&Bs[bk][bn] = b4;
        __syncthreads();
        #pragma unroll
        for (int kk = 0; kk < 16; kk++) {
            float4 av = *(const float4*)&Ast[kk][ty * 4];
            float4 bv = *(const float4*)&Bs[kk][tx * 4];
            float aa[4] = {av.x, av.y, av.z, av.w};
            float bb[4] = {bv.x, bv.y, bv.z, bv.w};
            #pragma unroll
            for (int i = 0; i < 4; i++)
                #pragma unroll
                for (int j = 0; j < 4; j++)
                    acc[i][j] += aa[i] * bb[j];
        }
        __syncthreads();
    }
    #pragma unroll
    for (int i = 0; i < 4; i++) {
        const int m = m0 + ty * 4 + i;
        #pragma unroll
        for (int j = 0; j < 4; j++) {
            const int n = n0 + tx * 4 + j;
            C[(size_t)m * N + n] = acc[i][j] + bias[n];
        }
    }
}

// ---------------- V projection GEMM: writes transposed fp16 g_vt[n][m] ----------------
__global__ __launch_bounds__(256) void gemm_bias_vt_kernel(
    const float* __restrict__ A, const float* __restrict__ B,
    const float* __restrict__ bias, int M, int K, int N)
{
    __shared__ float Ast[16][68];
    __shared__ float Bs[16][64];

    const int tid = threadIdx.x;
    const int tx = tid & 15, ty = tid >> 4;
    const int n0 = blockIdx.x * 64, m0 = blockIdx.y * 64;

    const int am = tid >> 2;
    const int ak = (tid & 3) * 4;
    const int bk = tid >> 4;
    const int bn = (tid & 15) * 4;

    float acc[4][4] = {};

    for (int k0 = 0; k0 < K; k0 += 16) {
        float4 a4 = *(const float4*)(A + (size_t)(m0 + am) * K + k0 + ak);
        Ast[ak + 0][am] = a4.x; Ast[ak + 1][am] = a4.y;
        Ast[ak + 2][am] = a4.z; Ast[ak + 3][am] = a4.w;
        float4 b4 = *(const float4*)(B + (size_t)(k0 + bk) * N + n0 + bn);
        *(float4*)&Bs[bk][bn] = b4;
        __syncthreads();
        #pragma unroll
        for (int kk = 0; kk < 16; kk++) {
            float4 av = *(const float4*)&Ast[kk][ty * 4];
            float4 bv = *(const float4*)&Bs[kk][tx * 4];
            float aa[4] = {av.x, av.y, av.z, av.w};
            float bb[4] = {bv.x, bv.y, bv.z, bv.w};
            #pragma unroll
            for (int i = 0; i < 4; i++)
                #pragma unroll
                for (int j = 0; j < 4; j++)
                    acc[i][j] += aa[i] * bb[j];
        }
        __syncthreads();
    }
    const int m = m0 + ty * 4;
    #pragma unroll
    for (int j = 0; j < 4; j++) {
        const int n = n0 + tx * 4 + j;
        const float bj = bias[n];
        uint2 w;
        w.x = h2pack(acc[0][j] + bj, acc[1][j] + bj);
        w.y = h2pack(acc[2][j] + bj, acc[3][j] + bj);
        *(uint2*)((char*)g_vt + ((size_t)n * NN + m) * 2) = w;
    }
}

// ---------------- fused attention: O = softmax(QK^T + bias, mask) V ----------------
// CTA = 128 rows x 1 head, 8 warps, 64-key tiles.
// Phase A: warp = 16 rows; fp16 mma S, exp -> fp16 P into CTA-wide PS smem,
//          l accumulated per-thread from ROUNDED values (rows warp-resident).
// Phase B: warp = (rowgroup warp&3, dm-half warp>>2); P@V via ldmatrix + mma.
// smem bytes: KT 2x5120 | VT 2x18432 | PS 18432 | LR 512  => 66048
#define F_KT    0
#define F_VT    10240
#define F_PS    47104
#define F_LR    65536
#define F_SMEM  66048

__global__ __launch_bounds__(256, 2) void attn_fused_kernel(const float* __restrict__ ebias)
{
    extern __shared__ unsigned char smf[];

    const int tid  = threadIdx.x;
    const int lane = tid & 31;
    const int warp = tid >> 5;
    const int g    = lane >> 2;
    const int tig  = lane & 3;
    const int head = blockIdx.y;
    const int row0 = blockIdx.x * 128;
    const int r1   = row0 + warp * 16 + g;     // phase-A rows
    const int r2   = r1 + 8;
    const int rg   = (warp & 3) * 32;          // phase-B local row base
    const int dof  = (warp >> 2) * 64;         // phase-B dm offset
    const float ESH = 4.1588830833596715f;     // 6*ln2

    const int skey = tid >> 2;                 // KT staging: key row 0..63
    const int sseg = tid & 3;                  // KT staging: 8-dim segment

    const uint32_t smb = (uint32_t)__cvta_generic_to_shared(smf);
    __half* KT = (__half*)(smf + F_KT);
    __half* PS = (__half*)(smf + F_PS);
    float*  LR = (float*)(smf + F_LR);

    // ldmatrix lane addressing
    const int aquad   = lane >> 4;
    const int arow_in = lane & 15;
    const int bquad   = lane >> 3;
    const int brow_in = (lane & 7) + ((bquad >> 1) << 3);
    const int bkcol   = (bquad & 1) << 3;

    // Q fragments (scaled, fp16) from fp32 g_q
    uint32_t qa[2][4];
    {
        const float qs = 0.17677669529663687f;
        const float* q1 = g_q + (size_t)r1 * 256 + head * 32;
        const float* q2 = g_q + (size_t)r2 * 256 + head * 32;
        #pragma unroll
        for (int ks = 0; ks < 2; ks++) {
            const int k0 = ks * 16 + 2 * tig;
            qa[ks][0] = h2pack(q1[k0] * qs,     q1[k0 + 1] * qs);
            qa[ks][1] = h2pack(q2[k0] * qs,     q2[k0 + 1] * qs);
            qa[ks][2] = h2pack(q1[k0 + 8] * qs, q1[k0 + 9] * qs);
            qa[ks][3] = h2pack(q2[k0 + 8] * qs, q2[k0 + 9] * qs);
        }
    }

    float o[2][8][4] = {};
    float la1 = 0.f, la2 = 0.f;

    const char* vv0 = (const char*)(g_vt + (size_t)(head * 128) * NN);

    // VT cp.async: 128 dm-rows x 64 keys fp16, row = 128B = 8 x 16B chunks
    #define FVT_ISSUE(t, buf) do {                                               \
        _Pragma("unroll")                                                        \
        for (int it = 0; it < 4; it++) {                                         \
            int idx = it * 256 + tid, d = idx >> 3, ch = idx & 7;                \
            cp_async16(smb + F_VT + (buf) * 18432 + d * 144 + ch * 16,           \
                       vv0 + (size_t)d * (NN * 2) + (size_t)(t) * 128 + ch * 16);\
        }                                                                        \
        asm volatile("cp.async.commit_group;");                                  \
    } while (0)

    // prologue: KT[0] stage + VT(0) issue
    {
        const float* kp = g_k + (size_t)skey * 256 + head * 32 + sseg * 8;
        float4 k0 = *(const float4*)kp;
        float4 k1 = *(const float4*)(kp + 4);
        uint4 w;
        w.x = h2pack(k0.x, k0.y); w.y = h2pack(k0.z, k0.w);
        w.z = h2pack(k1.x, k1.y); w.w = h2pack(k1.z, k1.w);
        *(uint4*)&KT[skey * 40 + sseg * 8] = w;
        FVT_ISSUE(0, 0);
    }
    __syncthreads();

    for (int t = 0; t < NN / 64; ++t) {
        const int cur = t & 1;
        const bool pf = (t + 1 < NN / 64);

        float4 pk0, pk1;
        if (pf) {
            FVT_ISSUE(t + 1, cur ^ 1);
            const float* kp = g_k + (size_t)((t + 1) * 64 + skey) * 256 + head * 32 + sseg * 8;
            pk0 = *(const float4*)kp;
            pk1 = *(const float4*)(kp + 4);
        }

        // ---- phase A: S -> exp -> PS (two 32-key halves to limit registers) ----
        const uint32_t ktc = smb + F_KT + cur * 5120;
        #pragma unroll
        for (int h = 0; h < 2; ++h) {
            float s[4][4];
            #pragma unroll
            for (int nb = 0; nb < 4; nb++) { s[nb][0] = s[nb][1] = s[nb][2] = s[nb][3] = 0.f; }
            #pragma unroll
            for (int ks = 0; ks < 2; ks++) {
                #pragma unroll
                for (int j = 0; j < 2; j++) {
                    uint32_t br[4];
                    const int krow = (2 * h + j) * 16 + brow_in;
                    ldmx4(br, ktc + (krow * 40 + ks * 16 + bkcol) * 2);
                    mma_f16(s[2 * j],     qa[ks], br[0], br[1]);
                    mma_f16(s[2 * j + 1], qa[ks], br[2], br[3]);
                }
            }
            const int col0 = t * 64 + h * 32;
            if (head == 0) {
                #pragma unroll
                for (int nb = 0; nb < 4; nb++) {
                    float2 b01 = *(const float2*)(ebias + (size_t)r1 * NN + col0 + nb * 8 + 2 * tig);
                    float2 b23 = *(const float2*)(ebias + (size_t)r2 * NN + col0 + nb * 8 + 2 * tig);
                    s[nb][0] += b01.x; s[nb][1] += b01.y;
                    s[nb][2] += b23.x; s[nb][3] += b23.y;
                }
            }
            {
                const unsigned w1 = g_maskbits[(size_t)(2 * t + h) * NN + r1];
                const unsigned w2 = g_maskbits[(size_t)(2 * t + h) * NN + r2];
                #pragma unroll
                for (int nb = 0; nb < 4; nb++) {
                    const int c = nb * 8 + 2 * tig;
                    if ((w1 >> c) & 1u)       s[nb][0] = -1e9f;
                    if ((w1 >> (c + 1)) & 1u) s[nb][1] = -1e9f;
                    if ((w2 >> c) & 1u)       s[nb][2] = -1e9f;
                    if ((w2 >> (c + 1)) & 1u) s[nb][3] = -1e9f;
                }
            }
            #pragma unroll
            for (int nb = 0; nb < 4; nb++) {
                float p0 = __expf(s[nb][0] - ESH);
                float p1 = __expf(s[nb][1] - ESH);
                float p2 = __expf(s[nb][2] - ESH);
                float p3 = __expf(s[nb][3] - ESH);
                unsigned u1 = h2pack(p0, p1);
                unsigned u2 = h2pack(p2, p3);
                __half2 h1 = *reinterpret_cast<__half2*>(&u1);
                __half2 h2v = *reinterpret_cast<__half2*>(&u2);
                float2 f1 = __half22float2(h1);
                float2 f2 = __half22float2(h2v);
                la1 += f1.x + f1.y;
                la2 += f2.x + f2.y;
                const int c = h * 32 + nb * 8 + 2 * tig;
                *(unsigned*)(PS + (warp * 16 + g) * 72 + c)     = u1;
                *(unsigned*)(PS + (warp * 16 + g + 8) * 72 + c) = u2;
            }
        }

        // ensure VT(t) arrived, PS visible to all warps
        if (pf) asm volatile("cp.async.wait_group 1;");
        else    asm volatile("cp.async.wait_group 0;");
        __syncthreads();

        // ---- phase B: O += P V ----
        {
            const uint32_t psb = smb + F_PS;
            const uint32_t vtb = smb + F_VT + cur * 18432;
            #pragma unroll
            for (int kf = 0; kf < 4; kf++) {
                uint32_t a0r[4], a1r[4];
                ldmx4(a0r, psb + ((rg + arow_in) * 72 + kf * 16 + aquad * 8) * 2);
                ldmx4(a1r, psb + ((rg + 16 + arow_in) * 72 + kf * 16 + aquad * 8) * 2);
                #pragma unroll
                for (int nbp = 0; nbp < 4; nbp++) {
                    uint32_t br[4];
                    const int nrow = dof + nbp * 16 + brow_in;
                    ldmx4(br, vtb + (nrow * 72 + kf * 16 + bkcol) * 2);
                    mma_f16(o[0][2 * nbp],     a0r, br[0], br[1]);
                    mma_f16(o[0][2 * nbp + 1], a0r, br[2], br[3]);
                    mma_f16(o[1][2 * nbp],     a1r, br[0], br[1]);
                    mma_f16(o[1][2 * nbp + 1], a1r, br[2], br[3]);
                }
            }
        }

        // store prefetched K into other KT buffer
        if (pf) {
            uint4 w;
            w.x = h2pack(pk0.x, pk0.y); w.y = h2pack(pk0.z, pk0.w);
            w.z = h2pack(pk1.x, pk1.y); w.w = h2pack(pk1.z, pk1.w);
            *(uint4*)&KT[(cur ^ 1) * 2560 + skey * 40 + sseg * 8] = w;
        }
        __syncthreads();
    }

    // ---- l reduction to smem (phase-A mapping) ----
    la1 += __shfl_xor_sync(0xffffffffu, la1, 1);
    la1 += __shfl_xor_sync(0xffffffffu, la1, 2);
    la2 += __shfl_xor_sync(0xffffffffu, la2, 1);
    la2 += __shfl_xor_sync(0xffffffffu, la2, 2);
    if (tig == 0) {
        LR[warp * 16 + g]     = la1;
        LR[warp * 16 + g + 8] = la2;
    }
    __syncthreads();

    // ---- epilogue (phase-B mapping): scale by 1/l, write fp16 g_attnh ----
    #pragma unroll
    for (int f = 0; f < 2; f++) {
        const int lr1 = rg + f * 16 + g;
        const int lr2 = lr1 + 8;
        const float i1 = 1.f / LR[lr1];
        const float i2 = 1.f / LR[lr2];
        __half* p1 = g_attnh + (size_t)(row0 + lr1) * 1024 + head * 128 + dof;
        __half* p2 = g_attnh + (size_t)(row0 + lr2) * 1024 + head * 128 + dof;
        #pragma unroll
        for (int nb = 0; nb < 8; nb++) {
            const int c = nb * 8 + 2 * tig;
            *(unsigned*)(p1 + c) = h2pack(o[f][nb][0] * i1, o[f][nb][1] * i1);
            *(unsigned*)(p2 + c) = h2pack(o[f][nb][2] * i2, o[f][nb][3] * i2);
        }
    }
}

// ---------------- out projection: out = attnh @ Wo + bo (fp16 mma, K=1024) --------
#define P2_BUF   18432
#define P2_VTOFF 36864
#define P2_SMEM  73728

__global__ __launch_bounds__(256, 2) void outproj_kernel(const float* __restrict__ bo,
                                                         float* __restrict__ out)
{
    extern __shared__ unsigned char sm2[];

    const int tid  = threadIdx.x;
    const int lane = tid & 31;
    const int warp = tid >> 5;
    const int g    = lane >> 2;
    const int tig  = lane & 3;
    const int row0 = blockIdx.x * 128;
    const int rg   = (warp & 3) * 32;
    const int dof  = (warp >> 2) * 64;

    const uint32_t smb = (uint32_t)__cvta_generic_to_shared(sm2);
    const char* ap = (const char*)g_attnh + (size_t)row0 * 2048;
    const char* bp = (const char*)g_wot;

    const int aquad   = lane >> 4;
    const int arow_in = lane & 15;
    const int bquad   = lane >> 3;
    const int brow_in = (lane & 7) + ((bquad >> 1) << 3);
    const int bkcol   = (bquad & 1) << 3;

    float o[2][8][4] = {};

    #define OISSUE(t, buf) do {                                                  \
        _Pragma("unroll")                                                        \
        for (int it = 0; it < 4; it++) {                                         \
            int idx = it * 256 + tid, r = idx >> 3, ch = idx & 7;                \
            cp_async16(smb + (buf) * P2_BUF + r * 144 + ch * 16,                 \
                       ap + (size_t)r * 2048 + (t) * 128 + ch * 16);             \
            cp_async16(smb + P2_VTOFF + (buf) * P2_BUF + r * 144 + ch * 16,      \
                       bp + (size_t)r * 2048 + (t) * 128 + ch * 16);             \
        }                                                                        \
        asm volatile("cp.async.commit_group;");                                  \
    } while (0)

    OISSUE(0, 0);

    for (int t = 0; t < 16; ++t) {
        const int cur = t & 1;
        if (t + 1 < 16) {
            OISSUE(t + 1, cur ^ 1);
            asm volatile("cp.async.wait_group 1;");
        } else {
            asm volatile("cp.async.wait_group 0;");
        }
        __syncthreads();

        const uint32_t psb = smb + cur * P2_BUF;
        const uint32_t vtb = smb + P2_VTOFF + cur * P2_BUF;
        #pragma unroll
        for (int kf = 0; kf < 4; kf++) {
            uint32_t a0r[4], a1r[4];
            ldmx4(a0r, psb + ((rg + arow_in) * 72 + kf * 16 + aquad * 8) * 2);
            ldmx4(a1r, psb + ((rg + 16 + arow_in) * 72 + kf * 16 + aquad * 8) * 2);
            #pragma unroll
            for (int nbp = 0; nbp < 4; nbp++) {
                uint32_t br[4];
                const int nrow = dof + nbp * 16 + brow_in;
                ldmx4(br, vtb + (nrow * 72 + kf * 16 + bkcol) * 2);
                mma_f16(o[0][2 * nbp],     a0r, br[0], br[1]);
                mma_f16(o[0][2 * nbp + 1], a0r, br[2], br[3]);
                mma_f16(o[1][2 * nbp],     a1r, br[0], br[1]);
                mma_f16(o[1][2 * nbp + 1], a1r, br[2], br[3]);
            }
        }
        __syncthreads();
    }

    #pragma unroll
    for (int f = 0; f < 2; f++) {
        const int lr1 = rg + f * 16 + g, lr2 = lr1 + 8;
        #pragma unroll
        for (int nb = 0; nb < 8; nb++) {
            const int c = dof + nb * 8 + 2 * tig;
            const float b0 = bo[c], b1 = bo[c + 1];
            float2 va; va.x = o[f][nb][0] + b0; va.y = o[f][nb][1] + b1;
            float2 vb; vb.x = o[f][nb][2] + b0; vb.y = o[f][nb][3] + b1;
            *(float2*)(out + (size_t)(row0 + lr1) * 128 + c) = va;
            *(float2*)(out + (size_t)(row0 + lr2) * 128 + c) = vb;
        }
    }
}

// ---------------- launch ----------------
extern "C" void kernel_launch(void* const* d_in, const int* in_sizes, int n_in,
                              void* d_out, int out_size)
{
    const float* x     = (const float*)d_in[0];
    const void*  mask  = (const void*) d_in[1];
    const float* ebias = (const float*)d_in[2];
    const float* Wq    = (const float*)d_in[3];
    const float* bq    = (const float*)d_in[4];
    const float* Wk    = (const float*)d_in[5];
    const float* bk    = (const float*)d_in[6];
    const float* Wv    = (const float*)d_in[7];
    const float* bv    = (const float*)d_in[8];
    const float* Wo    = (const float*)d_in[9];
    const float* bo    = (const float*)d_in[10];
    float* out = (float*)d_out;

    float *gq, *gk;
    __half *wot;
    cudaGetSymbolAddress((void**)&gq, g_q);
    cudaGetSymbolAddress((void**)&gk, g_k);
    cudaGetSymbolAddress((void**)&wot, g_wot);

    static bool attr_done = false;
    if (!attr_done) {
        cudaFuncSetAttribute(attn_fused_kernel, cudaFuncAttributeMaxDynamicSharedMemorySize,
                             F_SMEM);
        cudaFuncSetAttribute(outproj_kernel, cudaFuncAttributeMaxDynamicSharedMemorySize,
                             P2_SMEM);
        attr_done = true;
    }

    detect_mask_kernel<<<1, 32>>>((const unsigned*)mask);
    pack_mask_kernel<<<((NN / 32) * NN + 255) / 256, 256>>>(mask);

    gemm_bias_kernel<<<dim3(256 / 64, NN / 64), 256>>>(x, Wq, bq, gq, NN, DM, QK * HEADS);
    gemm_bias_kernel<<<dim3(256 / 64, NN / 64), 256>>>(x, Wk, bk, gk, NN, DM, QK * HEADS);
    gemm_bias_vt_kernel<<<dim3(1024 / 64, NN / 64), 256>>>(x, Wv, bv, NN, DM, DM * HEADS);
    transposew_kernel<<<(1024 * 128 + 255) / 256, 256>>>(Wo, wot, 1024, 128);

    attn_fused_kernel<<<dim3(NN / 128, HEADS), 256, F_SMEM>>>(ebias);

    outproj_kernel<<<NN / 128, 256, P2_SMEM>>>(bo, out);
}

// round 14
// speedup vs baseline: 1.6435x; 1.1711x over previous
#include <cuda_runtime.h>
#include <cuda_bf16.h>
#include <cuda_fp16.h>
#include <cstdint>

#define NN     4096
#define DM     128
#define QK     32
#define HEADS  8

// ---------------- device scratch (no allocation allowed) ----------------
__device__ static __half         g_xh[NN * 128];                  // x fp16
__device__ static __half         g_qh[NN * 256];                  // Q*qs fp16 [node][h*32+d]
__device__ static __half         g_kh[NN * 256];                  // K fp16
__device__ static __half         g_vt[(size_t)1024 * NN];         // [h*128+d][node], fp16
__device__ static __half         g_attnh[(size_t)NN * 1024];      // attention out, fp16
__device__ static __half         g_wqt[256 * 128];                // W^T fp16 [out][in]
__device__ static __half         g_wkt[256 * 128];
__device__ static __half         g_wvt[1024 * 128];
__device__ static __half         g_wot[128 * 1024];
__device__ static unsigned       g_maskbits[(NN / 32) * NN];      // [wordIdx][row]
__device__ static int            g_mask_mode;

// ---------------- helpers ----------------
__device__ __forceinline__ void mma_f16(float* d, const uint32_t* a, uint32_t b0, uint32_t b1)
{
    asm volatile("mma.sync.aligned.m16n8k16.row.col.f32.f16.f16.f32 "
                 "{%0,%1,%2,%3}, {%4,%5,%6,%7}, {%8,%9}, {%0,%1,%2,%3};"
                 : "+f"(d[0]), "+f"(d[1]), "+f"(d[2]), "+f"(d[3])
                 : "r"(a[0]), "r"(a[1]), "r"(a[2]), "r"(a[3]), "r"(b0), "r"(b1));
}
__device__ __forceinline__ void ldmx4(uint32_t* r, uint32_t addr)
{
    asm volatile("ldmatrix.sync.aligned.m8n8.x4.shared.b16 {%0,%1,%2,%3}, [%4];"
                 : "=r"(r[0]), "=r"(r[1]), "=r"(r[2]), "=r"(r[3]) : "r"(addr));
}
__device__ __forceinline__ unsigned h2pack(float lo, float hi) {
    __half2 h = __floats2half2_rn(lo, hi);
    return *reinterpret_cast<unsigned*>(&h);
}
__device__ __forceinline__ void cp_async16(uint32_t smem_u32, const void* gptr) {
    asm volatile("cp.async.cg.shared.global [%0], [%1], 16;" :: "r"(smem_u32), "l"(gptr));
}

// ---------------- mask dtype detection ----------------
__global__ void detect_mask_kernel(const unsigned* __restrict__ m) {
    if (threadIdx.x == 0) {
        bool is_i32 = true, is_f32 = true;
        for (int i = 0; i < 256; i++) {
            unsigned w = m[i];
            if (w > 1u) is_i32 = false;
            if (w != 0u && w != 0x3F800000u) is_f32 = false;
        }
        g_mask_mode = is_i32 ? 1 : (is_f32 ? 2 : 0);
    }
}

// ---------------- mask bit packing (transposed output) ----------------
__global__ void pack_mask_kernel(const void* __restrict__ mraw) {
    int gid = blockIdx.x * blockDim.x + threadIdx.x;
    if (gid >= (NN / 32) * NN) return;
    int r  = gid & (NN - 1);
    int wi = gid >> 12;
    int mode = g_mask_mode;
    size_t base = (size_t)r * NN + (size_t)wi * 32;
    unsigned bits = 0;
    if (mode == 1) {
        const int* p = (const int*)mraw;
        #pragma unroll
        for (int b = 0; b < 32; b++) bits |= (unsigned)(p[base + b] != 0) << b;
    } else if (mode == 2) {
        const float* p = (const float*)mraw;
        #pragma unroll
        for (int b = 0; b < 32; b++) bits |= (unsigned)(p[base + b] != 0.0f) << b;
    } else {
        const unsigned char* p = (const unsigned char*)mraw;
        #pragma unroll
        for (int b = 0; b < 32; b++) bits |= (unsigned)(p[base + b] != 0) << b;
    }
    g_maskbits[(size_t)wi * NN + r] = bits;
}

// ---------------- prep kernels ----------------
__global__ void convert_x_kernel(const float* __restrict__ x) {
    int gid = blockIdx.x * 256 + threadIdx.x;
    if (gid < NN * 128) g_xh[gid] = __float2half(x[gid]);
}
// W [K][N] fp32 -> Wt [N][K] fp16
__global__ void transposew_kernel(const float* __restrict__ W, __half* __restrict__ Wt,
                                  int K, int N) {
    int gid = blockIdx.x * 256 + threadIdx.x;
    if (gid >= K * N) return;
    int n = gid / K, k = gid - n * K;
    Wt[gid] = __float2half(W[(size_t)k * N + n]);
}

// ---------------- hgemm128: C[row][col] = sum_k A[row][k] B[col][k], K=128 ----------
// A: [rows][128] fp16 K-major, B: [cols][128] fp16 K-major. 128x128 tile per CTA.
// bias_per_row: 0 -> bias[col], 1 -> bias[row]. Output fp16 with scale folded.
#define HG_BUF   18432
#define HG_BOFF  36864
#define HG_SMEM  73728

__global__ __launch_bounds__(256, 2) void hgemm128_kernel(
    const __half* __restrict__ A, const __half* __restrict__ B,
    const float* __restrict__ bias, int bias_per_row, float scale,
    __half* __restrict__ C, int ldc)
{
    extern __shared__ unsigned char sm2[];

    const int tid  = threadIdx.x;
    const int lane = tid & 31;
    const int warp = tid >> 5;
    const int g    = lane >> 2;
    const int tig  = lane & 3;
    const int row0 = blockIdx.y * 128;
    const int col0 = blockIdx.x * 128;
    const int rg   = (warp & 3) * 32;
    const int dof  = (warp >> 2) * 64;

    const uint32_t smb = (uint32_t)__cvta_generic_to_shared(sm2);
    const char* ap = (const char*)(A + (size_t)row0 * 128);
    const char* bp = (const char*)(B + (size_t)col0 * 128);

    // stage both 64-k tiles of A and B
    #pragma unroll
    for (int t = 0; t < 2; t++) {
        #pragma unroll
        for (int it = 0; it < 4; it++) {
            int idx = it * 256 + tid, r = idx >> 3, ch = idx & 7;
            cp_async16(smb + t * HG_BUF + r * 144 + ch * 16,
                       ap + (size_t)r * 256 + t * 128 + ch * 16);
            cp_async16(smb + HG_BOFF + t * HG_BUF + r * 144 + ch * 16,
                       bp + (size_t)r * 256 + t * 128 + ch * 16);
        }
        asm volatile("cp.async.commit_group;");
    }
    asm volatile("cp.async.wait_group 0;");
    __syncthreads();

    const int aquad   = lane >> 4;
    const int arow_in = lane & 15;
    const int bquad   = lane >> 3;
    const int brow_in = (lane & 7) + ((bquad >> 1) << 3);
    const int bkcol   = (bquad & 1) << 3;

    float o[2][8][4] = {};
    #pragma unroll
    for (int t = 0; t < 2; t++) {
        const uint32_t psb = smb + t * HG_BUF;
        const uint32_t vtb = smb + HG_BOFF + t * HG_BUF;
        #pragma unroll
        for (int kf = 0; kf < 4; kf++) {
            uint32_t a0r[4], a1r[4];
            ldmx4(a0r, psb + ((rg + arow_in) * 72 + kf * 16 + aquad * 8) * 2);
            ldmx4(a1r, psb + ((rg + 16 + arow_in) * 72 + kf * 16 + aquad * 8) * 2);
            #pragma unroll
            for (int nbp = 0; nbp < 4; nbp++) {
                uint32_t br[4];
                const int nrow = dof + nbp * 16 + brow_in;
                ldmx4(br, vtb + (nrow * 72 + kf * 16 + bkcol) * 2);
                mma_f16(o[0][2 * nbp],     a0r, br[0], br[1]);
                mma_f16(o[0][2 * nbp + 1], a0r, br[2], br[3]);
                mma_f16(o[1][2 * nbp],     a1r, br[0], br[1]);
                mma_f16(o[1][2 * nbp + 1], a1r, br[2], br[3]);
            }
        }
    }

    #pragma unroll
    for (int f = 0; f < 2; f++) {
        const int lr1 = row0 + rg + f * 16 + g, lr2 = lr1 + 8;
        #pragma unroll
        for (int nb = 0; nb < 8; nb++) {
            const int c = col0 + dof + nb * 8 + 2 * tig;
            float b00, b01, b10, b11;
            if (bias_per_row) { b00 = b01 = bias[lr1]; b10 = b11 = bias[lr2]; }
            else              { b00 = b10 = bias[c];  b01 = b11 = bias[c + 1]; }
            *(unsigned*)(C + (size_t)lr1 * ldc + c) =
                h2pack((o[f][nb][0] + b00) * scale, (o[f][nb][1] + b01) * scale);
            *(unsigned*)(C + (size_t)lr2 * ldc + c) =
                h2pack((o[f][nb][2] + b10) * scale, (o[f][nb][3] + b11) * scale);
        }
    }
}

// ---------------- fused attention: O = softmax(QK^T + bias, mask) V ----------------
// CTA = 128 rows x 1 head, 8 warps, 64-key tiles. fp16 Q/K inputs.
#define F_KT    0
#define F_VT    10240
#define F_PS    47104
#define F_LR    65536
#define F_SMEM  66048

__global__ __launch_bounds__(256, 2) void attn_fused_kernel(const float* __restrict__ ebias)
{
    extern __shared__ unsigned char smf[];

    const int tid  = threadIdx.x;
    const int lane = tid & 31;
    const int warp = tid >> 5;
    const int g    = lane >> 2;
    const int tig  = lane & 3;
    const int head = blockIdx.y;
    const int row0 = blockIdx.x * 128;
    const int r1   = row0 + warp * 16 + g;
    const int r2   = r1 + 8;
    const int rg   = (warp & 3) * 32;
    const int dof  = (warp >> 2) * 64;
    const float ESH = 4.1588830833596715f;   // 6*ln2

    const int skey = tid >> 2;
    const int sseg = tid & 3;

    const uint32_t smb = (uint32_t)__cvta_generic_to_shared(smf);
    __half* KT = (__half*)(smf + F_KT);
    __half* PS = (__half*)(smf + F_PS);
    float*  LR = (float*)(smf + F_LR);

    const int aquad   = lane >> 4;
    const int arow_in = lane & 15;
    const int bquad   = lane >> 3;
    const int brow_in = (lane & 7) + ((bquad >> 1) << 3);
    const int bkcol   = (bquad & 1) << 3;

    // Q fragments: direct fp16 loads (scale folded into projection)
    uint32_t qa[2][4];
    {
        const __half* q1 = g_qh + (size_t)r1 * 256 + head * 32;
        const __half* q2 = g_qh + (size_t)r2 * 256 + head * 32;
        #pragma unroll
        for (int ks = 0; ks < 2; ks++) {
            const int k0 = ks * 16 + 2 * tig;
            qa[ks][0] = *(const uint32_t*)(q1 + k0);
            qa[ks][1] = *(const uint32_t*)(q2 + k0);
            qa[ks][2] = *(const uint32_t*)(q1 + k0 + 8);
            qa[ks][3] = *(const uint32_t*)(q2 + k0 + 8);
        }
    }

    float o[2][8][4] = {};
    float la1 = 0.f, la2 = 0.f;

    const char* vv0 = (const char*)(g_vt + (size_t)(head * 128) * NN);

    #define FVT_ISSUE(t, buf) do {                                               \
        _Pragma("unroll")                                                        \
        for (int it = 0; it < 4; it++) {                                         \
            int idx = it * 256 + tid, d = idx >> 3, ch = idx & 7;                \
            cp_async16(smb + F_VT + (buf) * 18432 + d * 144 + ch * 16,           \
                       vv0 + (size_t)d * (NN * 2) + (size_t)(t) * 128 + ch * 16);\
        }                                                                        \
        asm volatile("cp.async.commit_group;");                                  \
    } while (0)

    // prologue
    {
        *(uint4*)&KT[skey * 40 + sseg * 8] =
            *(const uint4*)(g_kh + (size_t)skey * 256 + head * 32 + sseg * 8);
        FVT_ISSUE(0, 0);
    }
    __syncthreads();

    for (int t = 0; t < NN / 64; ++t) {
        const int cur = t & 1;
        const bool pf = (t + 1 < NN / 64);

        uint4 pk;
        if (pf) {
            FVT_ISSUE(t + 1, cur ^ 1);
            pk = *(const uint4*)(g_kh + (size_t)((t + 1) * 64 + skey) * 256
                                 + head * 32 + sseg * 8);
        }

        // ---- phase A: S -> exp -> PS (two 32-key halves) ----
        const uint32_t ktc = smb + F_KT + cur * 5120;
        #pragma unroll
        for (int h = 0; h < 2; ++h) {
            float s[4][4];
            #pragma unroll
            for (int nb = 0; nb < 4; nb++) { s[nb][0] = s[nb][1] = s[nb][2] = s[nb][3] = 0.f; }
            #pragma unroll
            for (int ks = 0; ks < 2; ks++) {
                #pragma unroll
                for (int j = 0; j < 2; j++) {
                    uint32_t br[4];
                    const int krow = (2 * h + j) * 16 + brow_in;
                    ldmx4(br, ktc + (krow * 40 + ks * 16 + bkcol) * 2);
                    mma_f16(s[2 * j],     qa[ks], br[0], br[1]);
                    mma_f16(s[2 * j + 1], qa[ks], br[2], br[3]);
                }
            }
            const int col0 = t * 64 + h * 32;
            if (head == 0) {
                #pragma unroll
                for (int nb = 0; nb < 4; nb++) {
                    float2 b01 = *(const float2*)(ebias + (size_t)r1 * NN + col0 + nb * 8 + 2 * tig);
                    float2 b23 = *(const float2*)(ebias + (size_t)r2 * NN + col0 + nb * 8 + 2 * tig);
                    s[nb][0] += b01.x; s[nb][1] += b01.y;
                    s[nb][2] += b23.x; s[nb][3] += b23.y;
                }
            }
            {
                const unsigned w1 = g_maskbits[(size_t)(2 * t + h) * NN + r1];
                const unsigned w2 = g_maskbits[(size_t)(2 * t + h) * NN + r2];
                #pragma unroll
                for (int nb = 0; nb < 4; nb++) {
                    const int c = nb * 8 + 2 * tig;
                    if ((w1 >> c) & 1u)       s[nb][0] = -1e9f;
                    if ((w1 >> (c + 1)) & 1u) s[nb][1] = -1e9f;
                    if ((w2 >> c) & 1u)       s[nb][2] = -1e9f;
                    if ((w2 >> (c + 1)) & 1u) s[nb][3] = -1e9f;
                }
            }
            #pragma unroll
            for (int nb = 0; nb < 4; nb++) {
                float p0 = __expf(s[nb][0] - ESH);
                float p1 = __expf(s[nb][1] - ESH);
                float p2 = __expf(s[nb][2] - ESH);
                float p3 = __expf(s[nb][3] - ESH);
                unsigned u1 = h2pack(p0, p1);
                unsigned u2 = h2pack(p2, p3);
                __half2 h1 = *reinterpret_cast<__half2*>(&u1);
                __half2 h2v = *reinterpret_cast<__half2*>(&u2);
                float2 f1 = __half22float2(h1);
                float2 f2 = __half22float2(h2v);
                la1 += f1.x + f1.y;
                la2 += f2.x + f2.y;
                const int c = h * 32 + nb * 8 + 2 * tig;
                *(unsigned*)(PS + (warp * 16 + g) * 72 + c)     = u1;
                *(unsigned*)(PS + (warp * 16 + g + 8) * 72 + c) = u2;
            }
        }

        if (pf) asm volatile("cp.async.wait_group 1;");
        else    asm volatile("cp.async.wait_group 0;");
        __syncthreads();

        // ---- phase B: O += P V ----
        {
            const uint32_t psb = smb + F_PS;
            const uint32_t vtb = smb + F_VT + cur * 18432;
            #pragma unroll
            for (int kf = 0; kf < 4; kf++) {
                uint32_t a0r[4], a1r[4];
                ldmx4(a0r, psb + ((rg + arow_in) * 72 + kf * 16 + aquad * 8) * 2);
                ldmx4(a1r, psb + ((rg + 16 + arow_in) * 72 + kf * 16 + aquad * 8) * 2);
                #pragma unroll
                for (int nbp = 0; nbp < 4; nbp++) {
                    uint32_t br[4];
                    const int nrow = dof + nbp * 16 + brow_in;
                    ldmx4(br, vtb + (nrow * 72 + kf * 16 + bkcol) * 2);
                    mma_f16(o[0][2 * nbp],     a0r, br[0], br[1]);
                    mma_f16(o[0][2 * nbp + 1], a0r, br[2], br[3]);
                    mma_f16(o[1][2 * nbp],     a1r, br[0], br[1]);
                    mma_f16(o[1][2 * nbp + 1], a1r, br[2], br[3]);
                }
            }
        }

        if (pf)
            *(uint4*)&KT[(cur ^ 1) * 2560 + skey * 40 + sseg * 8] = pk;
        __syncthreads();
    }

    // ---- l reduction to smem (phase-A mapping) ----
    la1 += __shfl_xor_sync(0xffffffffu, la1, 1);
    la1 += __shfl_xor_sync(0xffffffffu, la1, 2);
    la2 += __shfl_xor_sync(0xffffffffu, la2, 1);
    la2 += __shfl_xor_sync(0xffffffffu, la2, 2);
    if (tig == 0) {
        LR[warp * 16 + g]     = la1;
        LR[warp * 16 + g + 8] = la2;
    }
    __syncthreads();

    // ---- epilogue (phase-B mapping) ----
    #pragma unroll
    for (int f = 0; f < 2; f++) {
        const int lr1 = rg + f * 16 + g;
        const int lr2 = lr1 + 8;
        const float i1 = 1.f / LR[lr1];
        const float i2 = 1.f / LR[lr2];
        __half* p1 = g_attnh + (size_t)(row0 + lr1) * 1024 + head * 128 + dof;
        __half* p2 = g_attnh + (size_t)(row0 + lr2) * 1024 + head * 128 + dof;
        #pragma unroll
        for (int nb = 0; nb < 8; nb++) {
            const int c = nb * 8 + 2 * tig;
            *(unsigned*)(p1 + c) = h2pack(o[f][nb][0] * i1, o[f][nb][1] * i1);
            *(unsigned*)(p2 + c) = h2pack(o[f][nb][2] * i2, o[f][nb][3] * i2);
        }
    }
}

// ---------------- out projection: out = attnh @ Wo + bo (fp16 mma, K=1024) --------
#define P2_BUF   18432
#define P2_VTOFF 36864
#define P2_SMEM  73728

__global__ __launch_bounds__(256, 2) void outproj_kernel(const float* __restrict__ bo,
                                                         float* __restrict__ out)
{
    extern __shared__ unsigned char sm2[];

    const int tid  = threadIdx.x;
    const int lane = tid & 31;
    const int warp = tid >> 5;
    const int g    = lane >> 2;
    const int tig  = lane & 3;
    const int row0 = blockIdx.x * 128;
    const int rg   = (warp & 3) * 32;
    const int dof  = (warp >> 2) * 64;

    const uint32_t smb = (uint32_t)__cvta_generic_to_shared(sm2);
    const char* ap = (const char*)g_attnh + (size_t)row0 * 2048;
    const char* bp = (const char*)g_wot;

    const int aquad   = lane >> 4;
    const int arow_in = lane & 15;
    const int bquad   = lane >> 3;
    const int brow_in = (lane & 7) + ((bquad >> 1) << 3);
    const int bkcol   = (bquad & 1) << 3;

    float o[2][8][4] = {};

    #define OISSUE(t, buf) do {                                                  \
        _Pragma("unroll")                                                        \
        for (int it = 0; it < 4; it++) {                                         \
            int idx = it * 256 + tid, r = idx >> 3, ch = idx & 7;                \
            cp_async16(smb + (buf) * P2_BUF + r * 144 + ch * 16,                 \
                       ap + (size_t)r * 2048 + (t) * 128 + ch * 16);             \
            cp_async16(smb + P2_VTOFF + (buf) * P2_BUF + r * 144 + ch * 16,      \
                       bp + (size_t)r * 2048 + (t) * 128 + ch * 16);             \
        }                                                                        \
        asm volatile("cp.async.commit_group;");                                  \
    } while (0)

    OISSUE(0, 0);

    for (int t = 0; t < 16; ++t) {
        const int cur = t & 1;
        if (t + 1 < 16) {
            OISSUE(t + 1, cur ^ 1);
            asm volatile("cp.async.wait_group 1;");
        } else {
            asm volatile("cp.async.wait_group 0;");
        }
        __syncthreads();

        const uint32_t psb = smb + cur * P2_BUF;
        const uint32_t vtb = smb + P2_VTOFF + cur * P2_BUF;
        #pragma unroll
        for (int kf = 0; kf < 4; kf++) {
            uint32_t a0r[4], a1r[4];
            ldmx4(a0r, psb + ((rg + arow_in) * 72 + kf * 16 + aquad * 8) * 2);
            ldmx4(a1r, psb + ((rg + 16 + arow_in) * 72 + kf * 16 + aquad * 8) * 2);
            #pragma unroll
            for (int nbp = 0; nbp < 4; nbp++) {
                uint32_t br[4];
                const int nrow = dof + nbp * 16 + brow_in;
                ldmx4(br, vtb + (nrow * 72 + kf * 16 + bkcol) * 2);
                mma_f16(o[0][2 * nbp],     a0r, br[0], br[1]);
                mma_f16(o[0][2 * nbp + 1], a0r, br[2], br[3]);
                mma_f16(o[1][2 * nbp],     a1r, br[0], br[1]);
                mma_f16(o[1][2 * nbp + 1], a1r, br[2], br[3]);
            }
        }
        __syncthreads();
    }

    #pragma unroll
    for (int f = 0; f < 2; f++) {
        const int lr1 = rg + f * 16 + g, lr2 = lr1 + 8;
        #pragma unroll
        for (int nb = 0; nb < 8; nb++) {
            const int c = dof + nb * 8 + 2 * tig;
            const float b0 = bo[c], b1 = bo[c + 1];
            float2 va; va.x = o[f][nb][0] + b0; va.y = o[f][nb][1] + b1;
            float2 vb; vb.x = o[f][nb][2] + b0; vb.y = o[f][nb][3] + b1;
            *(float2*)(out + (size_t)(row0 + lr1) * 128 + c) = va;
            *(float2*)(out + (size_t)(row0 + lr2) * 128 + c) = vb;
        }
    }
}

// ---------------- launch ----------------
extern "C" void kernel_launch(void* const* d_in, const int* in_sizes, int n_in,
                              void* d_out, int out_size)
{
    const float* x     = (const float*)d_in[0];
    const void*  mask  = (const void*) d_in[1];
    const float* ebias = (const float*)d_in[2];
    const float* Wq    = (const float*)d_in[3];
    const float* bq    = (const float*)d_in[4];
    const float* Wk    = (const float*)d_in[5];
    const float* bk    = (const float*)d_in[6];
    const float* Wv    = (const float*)d_in[7];
    const float* bv    = (const float*)d_in[8];
    const float* Wo    = (const float*)d_in[9];
    const float* bo    = (const float*)d_in[10];
    float* out = (float*)d_out;

    __half *xh, *qh, *kh, *vt, *wqt, *wkt, *wvt, *wot;
    cudaGetSymbolAddress((void**)&xh,  g_xh);
    cudaGetSymbolAddress((void**)&qh,  g_qh);
    cudaGetSymbolAddress((void**)&kh,  g_kh);
    cudaGetSymbolAddress((void**)&vt,  g_vt);
    cudaGetSymbolAddress((void**)&wqt, g_wqt);
    cudaGetSymbolAddress((void**)&wkt, g_wkt);
    cudaGetSymbolAddress((void**)&wvt, g_wvt);
    cudaGetSymbolAddress((void**)&wot, g_wot);

    static bool attr_done = false;
    if (!attr_done) {
        cudaFuncSetAttribute(attn_fused_kernel, cudaFuncAttributeMaxDynamicSharedMemorySize,
                             F_SMEM);
        cudaFuncSetAttribute(outproj_kernel, cudaFuncAttributeMaxDynamicSharedMemorySize,
                             P2_SMEM);
        cudaFuncSetAttribute(hgemm128_kernel, cudaFuncAttributeMaxDynamicSharedMemorySize,
                             HG_SMEM);
        attr_done = true;
    }

    detect_mask_kernel<<<1, 32>>>((const unsigned*)mask);
    pack_mask_kernel<<<((NN / 32) * NN + 255) / 256, 256>>>(mask);

    convert_x_kernel<<<(NN * 128 + 255) / 256, 256>>>(x);
    transposew_kernel<<<(128 * 256 + 255) / 256, 256>>>(Wq, wqt, 128, 256);
    transposew_kernel<<<(128 * 256 + 255) / 256, 256>>>(Wk, wkt, 128, 256);
    transposew_kernel<<<(128 * 1024 + 255) / 256, 256>>>(Wv, wvt, 128, 1024);
    transposew_kernel<<<(1024 * 128 + 255) / 256, 256>>>(Wo, wot, 1024, 128);

    // Q: [4096x128] x [256x128] -> g_qh (scale folded); K likewise; V transposed direct.
    hgemm128_kernel<<<dim3(2, 32), 256, HG_SMEM>>>(xh, wqt, bq, 0, 0.17677669529663687f,
                                                   qh, 256);
    hgemm128_kernel<<<dim3(2, 32), 256, HG_SMEM>>>(xh, wkt, bk, 0, 1.0f, kh, 256);
    hgemm128_kernel<<<dim3(32, 8), 256, HG_SMEM>>>(wvt, xh, bv, 1, 1.0f, vt, NN);

    attn_fused_kernel<<<dim3(NN / 128, HEADS), 256, F_SMEM>>>(ebias);

    outproj_kernel<<<NN / 128, 256, P2_SMEM>>>(bo, out);
}